// round 10
// baseline (speedup 1.0000x reference)
#include <cuda_runtime.h>
#include <cuda_bf16.h>
#include <cstdint>

#define TOK   4096
#define DH    16384
#define DM    1024
#define KSEL  64
#define CMAX  192
#define RWIN  1.5e-2f

// ---- scratch (device globals; no runtime allocation) ----
__device__ float g_z[(long)TOK * DH];                        // 256 MB z~ (bf16-accurate)
__device__ __align__(16) __nv_bfloat16 g_Abf[(long)TOK * DM];
__device__ __align__(16) __nv_bfloat16 g_Bbf[(long)DH * DM]; // W_enc^T bf16
__device__ __align__(16) float         g_WT [(long)DH * DM]; // W_enc^T fp32 (exact recompute)

// ============================================================
// helpers
// ============================================================
__device__ __forceinline__ uint32_t smem_u32(const void* p) {
    uint32_t a;
    asm("{ .reg .u64 t; cvta.to.shared.u64 t, %1; cvt.u32.u64 %0, t; }"
        : "=r"(a) : "l"(p));
    return a;
}
#define SWZ128(o) ((o) ^ (((o) >> 3) & 0x70))

#define CPASYNC16(dst, src) \
    asm volatile("cp.async.cg.shared.global [%0], [%1], 16;" \
                 :: "r"(dst), "l"(src) : "memory")
#define CP_COMMIT() asm volatile("cp.async.commit_group;" ::: "memory")

#define MMA16816(c, a, b0, b1) \
    asm volatile("mma.sync.aligned.m16n8k16.row.col.f32.bf16.bf16.f32 " \
        "{%0,%1,%2,%3}, {%4,%5,%6,%7}, {%8,%9}, {%0,%1,%2,%3};" \
        : "+f"((c)[0]), "+f"((c)[1]), "+f"((c)[2]), "+f"((c)[3]) \
        : "r"((a)[0]), "r"((a)[1]), "r"((a)[2]), "r"((a)[3]), "r"(b0), "r"(b1))

#define LDMATX4(r, ad) \
    asm volatile("ldmatrix.sync.aligned.m8n8.x4.shared.b16 {%0,%1,%2,%3}, [%4];" \
        : "=r"((r)[0]), "=r"((r)[1]), "=r"((r)[2]), "=r"((r)[3]) : "r"(ad))

// ---- double-float exact-ish dot product, warp-cooperative ----
__device__ __forceinline__ void two_sum(float a, float b, float& s, float& e) {
    s = a + b;
    float bv = s - a;
    e = (a - (s - bv)) + (b - bv);
}
__device__ __forceinline__ double df_dot_warp(const float* __restrict__ x,
                                              const float* __restrict__ w,
                                              int lane) {
    float hi = 0.f, lo = 0.f;
    for (int k = lane; k < DM; k += 32) {
        float xv = x[k], wv = w[k];
        float p  = xv * wv;
        float pe = fmaf(xv, wv, -p);
        float s, e;
        two_sum(hi, p, s, e);
        lo += e + pe;
        hi = s;
    }
#pragma unroll
    for (int off = 16; off; off >>= 1) {
        float h2 = __shfl_down_sync(0xFFFFFFFFu, hi, off);
        float l2 = __shfl_down_sync(0xFFFFFFFFu, lo, off);
        float s, e;
        two_sum(hi, h2, s, e);
        lo = lo + l2 + e;
        hi = s;
    }
    return (double)hi + (double)lo;     // valid on lane 0
}

// ============================================================
// Prepass 1: x -> bf16
// ============================================================
__global__ __launch_bounds__(256) void split_x_kernel(const float* __restrict__ x)
{
    long i = (long)blockIdx.x * 256 + threadIdx.x;      // float4 index
    float4 v = ((const float4*)x)[i];
    __nv_bfloat16 h[4];
    h[0] = __float2bfloat16(v.x); h[1] = __float2bfloat16(v.y);
    h[2] = __float2bfloat16(v.z); h[3] = __float2bfloat16(v.w);
    ((uint2*)g_Abf)[i] = *(uint2*)h;
}

// ============================================================
// Prepass 2: transpose W_enc [DM,DH] -> [DH,DM] fp32 + bf16
// ============================================================
__global__ __launch_bounds__(256) void split_w_kernel(const float* __restrict__ W)
{
    __shared__ float s[32][33];
    const int n0 = blockIdx.x * 32, k0 = blockIdx.y * 32;
    const int tx = threadIdx.x, ty = threadIdx.y;   // 32 x 8
#pragma unroll
    for (int i = 0; i < 4; i++)
        s[ty + 8 * i][tx] = W[(long)(k0 + ty + 8 * i) * DH + n0 + tx];
    __syncthreads();
#pragma unroll
    for (int i = 0; i < 4; i++) {
        const int n = n0 + ty + 8 * i, k = k0 + tx;
        const float f = s[tx][ty + 8 * i];
        g_WT [(long)n * DM + k] = f;
        g_Bbf[(long)n * DM + k] = __float2bfloat16(f);
    }
}

// ============================================================
// Encode GEMM: bf16 mma.sync (HMMA), 128x256 CTA, 64x64 warps,
// BK=64, SW128 K-major smem, 3-stage cp.async pipeline. (R9)
// ============================================================
#define BM 128
#define BN 256
#define BKG 64
#define ASTG 16384
#define STAGE 49152
#define NSTG 3
#define SMEM_DYN (NSTG * STAGE)

__global__ __launch_bounds__(256, 1) void encode_mma_kernel(const float* __restrict__ bias)
{
    extern __shared__ __align__(1024) char smem[];
    const uint32_t smb = smem_u32(smem);
    const int tid = threadIdx.x, lane = tid & 31, wid = tid >> 5;
    const int wm = wid >> 2, wn = wid & 3;
    const int m0 = blockIdx.y * BM, n0 = blockIdx.x * BN;

    int arow[4], bro[8];
    uint32_t asw[4], bsw[8];
    long asrc[4], bsrc[8];
#pragma unroll
    for (int i = 0; i < 4; i++) {
        int c = tid + 256 * i;
        arow[i] = c >> 3;
        int ch = c & 7;
        asw[i] = SWZ128((uint32_t)(arow[i] * 128 + ch * 16));
        asrc[i] = (long)(m0 + arow[i]) * DM + ch * 8;
    }
#pragma unroll
    for (int i = 0; i < 8; i++) {
        int c = tid + 256 * i;
        bro[i] = c >> 3;
        int ch = c & 7;
        bsw[i] = SWZ128((uint32_t)(bro[i] * 128 + ch * 16));
        bsrc[i] = (long)(n0 + bro[i]) * DM + ch * 8;
    }

    const int rowA = wm * 64 + (lane & 7) + ((lane >> 3) & 1) * 8;
    const int kbA  = ((lane >> 4) & 1) * 16;
    const int rowB = wn * 64 + (lane & 7) + ((lane >> 4) & 1) * 8;
    const int kbB  = ((lane >> 3) & 1) * 16;

    float acc[4][8][4];
#pragma unroll
    for (int m = 0; m < 4; m++)
#pragma unroll
        for (int n = 0; n < 8; n++)
#pragma unroll
            for (int r = 0; r < 4; r++) acc[m][n][r] = 0.f;

    auto issue = [&](int k0, int s) {
        const uint32_t As = smb + s * STAGE;
        const uint32_t Bs = As + ASTG;
#pragma unroll
        for (int i = 0; i < 4; i++)
            CPASYNC16(As + asw[i], (const char*)(g_Abf + asrc[i] + k0));
#pragma unroll
        for (int i = 0; i < 8; i++)
            CPASYNC16(Bs + bsw[i], (const char*)(g_Bbf + bsrc[i] + k0));
    };

    auto compute = [&](int s) {
        const uint32_t As = smb + s * STAGE;
        const uint32_t Bs = As + ASTG;
#pragma unroll
        for (int ks = 0; ks < 4; ks++) {
            uint32_t a[4][4], bq[4][4];
#pragma unroll
            for (int mt = 0; mt < 4; mt++) {
                uint32_t off = (uint32_t)((rowA + mt * 16) * 128 + ks * 32 + kbA);
                LDMATX4(a[mt], As + SWZ128(off));
            }
#pragma unroll
            for (int j = 0; j < 4; j++) {
                uint32_t off = (uint32_t)((rowB + j * 16) * 128 + ks * 32 + kbB);
                LDMATX4(bq[j], Bs + SWZ128(off));
            }
#pragma unroll
            for (int mt = 0; mt < 4; mt++)
#pragma unroll
                for (int j = 0; j < 4; j++) {
                    MMA16816(acc[mt][2 * j],     a[mt], bq[j][0], bq[j][1]);
                    MMA16816(acc[mt][2 * j + 1], a[mt], bq[j][2], bq[j][3]);
                }
        }
    };

    issue(0, 0);   CP_COMMIT();
    issue(64, 1);  CP_COMMIT();

    const int NIT = DM / BKG;   // 16
    for (int i = 0; i < NIT; i++) {
        if (i < NIT - 2) asm volatile("cp.async.wait_group 1;" ::: "memory");
        else             asm volatile("cp.async.wait_group 0;" ::: "memory");
        __syncthreads();
        compute(i % NSTG);
        if (i + 2 < NIT) {
            issue((i + 2) * BKG, (i + 2) % NSTG);
            CP_COMMIT();
        }
    }

    const int r0  = m0 + wm * 64 + (lane >> 2);
    const int c0  = n0 + wn * 64 + (lane & 3) * 2;
#pragma unroll
    for (int nt = 0; nt < 8; nt++) {
        const int col = c0 + nt * 8;
        const float2 bv = *(const float2*)&bias[col];
#pragma unroll
        for (int mt = 0; mt < 4; mt++) {
            const int r = r0 + mt * 16;
            float2 o0, o1;
            o0.x = fmaxf(acc[mt][nt][0] + bv.x, 0.f);
            o0.y = fmaxf(acc[mt][nt][1] + bv.y, 0.f);
            o1.x = fmaxf(acc[mt][nt][2] + bv.x, 0.f);
            o1.y = fmaxf(acc[mt][nt][3] + bv.y, 0.f);
            *(float2*)&g_z[(long)r * DH + col]       = o0;
            *(float2*)&g_z[(long)(r + 8) * DH + col] = o1;
        }
    }
}

// ============================================================
// Fused TopK (2-level radix histogram + df exact refinement)
// + value recompute + decode.
// ============================================================
__global__ __launch_bounds__(256) void topk_decode_kernel(
    const float* __restrict__ X,      // x fp32 [TOK, DM]
    const float* __restrict__ benc,   // b_enc
    const float* __restrict__ Wd,     // W_dec [DH, DM]
    const float* __restrict__ bd,     // b_dec
    float* __restrict__ Y)            // out [TOK, DM]
{
    extern __shared__ unsigned sm[];   // DH values (64 KB)
    __shared__ int    s_hist[512];
    __shared__ int    s_suf[512];
    __shared__ int    s_scan[256];
    __shared__ int    s_cidx[CMAX];
    __shared__ double s_cval[CMAX];
    __shared__ int    s_selidx[KSEL];
    __shared__ float  s_selval[KSEL];
    __shared__ int    s_b1, s_b2, s_red, s_cnt;

    const int row = blockIdx.x;
    const int tid = threadIdx.x;
    const int wid = tid >> 5, lane = tid & 31;
    const float* xr = X + (long)row * DM;
    const int base = tid * (DH / 256);

    auto suffix_scan = [&]() {
        s_suf[tid] = s_hist[tid];
        s_suf[tid + 256] = s_hist[tid + 256];
        __syncthreads();
        for (int off = 1; off < 512; off <<= 1) {
            int v0 = (tid + off < 512) ? s_suf[tid + off] : 0;
            int v1 = (tid + 256 + off < 512) ? s_suf[tid + 256 + off] : 0;
            __syncthreads();
            s_suf[tid] += v0;
            s_suf[tid + 256] += v1;
            __syncthreads();
        }
    };
    auto prefix_scan256 = [&]() {       // inclusive, over s_scan
        for (int off = 1; off < 256; off <<= 1) {
            int v = (tid >= off) ? s_scan[tid - off] : 0;
            __syncthreads();
            s_scan[tid] += v;
            __syncthreads();
        }
    };

    // ---- stage row + L1 histogram (bits[30:22], zeros skipped) ----
    s_hist[tid] = 0; s_hist[tid + 256] = 0;
    if (tid == 0) { s_b1 = -1; s_b2 = -1; }
    __syncthreads();
    {
        const uint4* z4 = (const uint4*)(g_z + (long)row * DH);
        uint4* s4 = (uint4*)sm;
        for (int i = tid; i < DH / 4; i += 256) {
            uint4 u = z4[i];
            s4[i] = u;
            if (u.x) atomicAdd(&s_hist[u.x >> 22], 1);
            if (u.y) atomicAdd(&s_hist[u.y >> 22], 1);
            if (u.z) atomicAdd(&s_hist[u.z >> 22], 1);
            if (u.w) atomicAdd(&s_hist[u.w >> 22], 1);
        }
    }
    __syncthreads();
    suffix_scan();
#pragma unroll
    for (int r = 0; r < 2; r++) {
        int j = tid + 256 * r;
        if (s_suf[j] >= KSEL && (j == 511 || s_suf[j + 1] < KSEL)) s_b1 = j;
    }
    __syncthreads();
    const int b1 = s_b1;
    const int cab1 = (b1 >= 0 && b1 < 511) ? s_suf[b1 + 1] : 0;

    bool fast = false;
    int cA = 0;

    if (b1 >= 1) {
        // ---- L2 histogram on bits[21:13] within bin b1 ----
        s_hist[tid] = 0; s_hist[tid + 256] = 0;
        __syncthreads();
#pragma unroll 4
        for (int i = 0; i < DH / 256; i++) {
            unsigned v = sm[base + i];
            if ((int)(v >> 22) == b1) atomicAdd(&s_hist[(v >> 13) & 511], 1);
        }
        __syncthreads();
        suffix_scan();
#pragma unroll
        for (int r = 0; r < 2; r++) {
            int j = tid + 256 * r;
            if (cab1 + s_suf[j] >= KSEL &&
                (j == 511 || cab1 + s_suf[j + 1] < KSEL)) s_b2 = j;
        }
        __syncthreads();
        const int b2 = s_b2;
        const unsigned tlb = ((unsigned)b1 << 22) | ((unsigned)b2 << 13);
        const float tf_lo = __uint_as_float(tlb);
        const float w2 = __uint_as_float(tlb + (1u << 13)) - tf_lo;

        if (tf_lo > 2.0f * RWIN) {
            const unsigned hib = __float_as_uint(tf_lo + w2 + RWIN);
            const unsigned lob = __float_as_uint(tf_lo - RWIN);

            // ---- one pass: count A (v>hib) and candidates ([lob,hib]) ----
            int ng = 0, nc = 0;
#pragma unroll 4
            for (int i = 0; i < DH / 256; i++) {
                unsigned v = sm[base + i];
                ng += (v > hib) ? 1 : 0;
                nc += (v >= lob && v <= hib) ? 1 : 0;
            }
            // scan + compact A (ascending index)
            s_scan[tid] = ng;
            __syncthreads();
            prefix_scan256();
            cA = s_scan[255];
            {
                int w = s_scan[tid] - ng;
                for (int i = 0; i < DH / 256; i++) {
                    unsigned v = sm[base + i];
                    if (v > hib) s_selidx[w++] = base + i;
                }
            }
            __syncthreads();
            // scan + compact candidates
            s_scan[tid] = nc;
            __syncthreads();
            prefix_scan256();
            const int cC = s_scan[255];
            if (cC <= CMAX) {
                int w = s_scan[tid] - nc;
                for (int i = 0; i < DH / 256; i++) {
                    unsigned v = sm[base + i];
                    if (v >= lob && v <= hib) s_cidx[w++] = base + i;
                }
                __syncthreads();

                // exact df values for candidates (warp per candidate)
                for (int c = wid; c < cC; c += 8) {
                    const int fi = s_cidx[c];
                    double d = df_dot_warp(xr, g_WT + (long)fi * DM, lane);
                    if (lane == 0) {
                        d += (double)benc[fi];
                        s_cval[c] = d > 0.0 ? d : 0.0;
                    }
                }
                __syncthreads();

                // rank candidates (value desc, index asc); keep top need
                const int need = KSEL - cA;
                for (int c = tid; c < cC; c += 256) {
                    const double v = s_cval[c];
                    const int fi = s_cidx[c];
                    int rank = 0;
                    for (int c2 = 0; c2 < cC; c2++) {
                        const double u = s_cval[c2];
                        if (u > v || (u == v && s_cidx[c2] < fi)) rank++;
                    }
                    if (rank < need) s_selidx[cA + rank] = fi;
                }
                __syncthreads();

                // exact df recompute of ALL selected values
                for (int j = wid; j < KSEL; j += 8) {
                    const int fi = s_selidx[j];
                    double d = df_dot_warp(xr, g_WT + (long)fi * DM, lane);
                    if (lane == 0) {
                        d += (double)benc[fi];
                        s_selval[j] = (float)(d > 0.0 ? d : 0.0);
                    }
                }
                if (tid == 0) s_cnt = KSEL;
                fast = true;
            }
            __syncthreads();
        }
    }

    if (!fast) {
        // ---- fallback: exact rank-64 of z~ via binary search (rare) ----
        unsigned lo = 0u, hi = 0x7F800000u;
        while (lo < hi) {
            unsigned mid = lo + ((hi - lo + 1) >> 1);
            if (tid == 0) s_red = 0;
            __syncthreads();
            int c = 0;
#pragma unroll 8
            for (int i = 0; i < DH / 256; i++)
                c += (sm[i * 256 + tid] >= mid) ? 1 : 0;
#pragma unroll
            for (int o = 16; o; o >>= 1) c += __shfl_xor_sync(0xFFFFFFFFu, c, o);
            if ((tid & 31) == 0) atomicAdd(&s_red, c);
            __syncthreads();
            int cnt = s_red;
            if (cnt >= KSEL) lo = mid; else hi = mid - 1;
            __syncthreads();
        }
        const unsigned t = lo;

        int ng = 0;
#pragma unroll 8
        for (int i = 0; i < DH / 256; i++) ng += (sm[base + i] > t) ? 1 : 0;
        s_scan[tid] = ng;
        __syncthreads();
        prefix_scan256();
        const int c_gt = s_scan[255];
        {
            int w = s_scan[tid] - ng;
            for (int i = 0; i < DH / 256; i++) {
                unsigned v = sm[base + i];
                if (v > t) {
                    s_selidx[w] = base + i;
                    s_selval[w] = __uint_as_float(v);
                    w++;
                }
            }
        }
        int cnt_final = c_gt;
        if (t != 0u) {
            __syncthreads();
            int ne = 0;
#pragma unroll 8
            for (int i = 0; i < DH / 256; i++) ne += (sm[base + i] == t) ? 1 : 0;
            s_scan[tid] = ne;
            __syncthreads();
            prefix_scan256();
            int pos = c_gt + s_scan[tid] - ne;
            for (int i = 0; i < DH / 256; i++) {
                if (sm[base + i] == t) {
                    if (pos < KSEL) {
                        s_selidx[pos] = base + i;
                        s_selval[pos] = __uint_as_float(t);
                    }
                    pos++;
                }
            }
            cnt_final = KSEL;
        }
        if (tid == 0) s_cnt = cnt_final;
    }

    // ---- fused decode: y = b_dec + sum val_j * W_dec[idx_j,:] ----
    __syncthreads();
    const int cnt = s_cnt;
    float4 acc = ((const float4*)bd)[tid];
#pragma unroll 4
    for (int j = 0; j < cnt; j++) {
        const float v = s_selval[j];
        const float4 wv = ((const float4*)(Wd + (long)s_selidx[j] * DM))[tid];
        acc.x = fmaf(v, wv.x, acc.x);
        acc.y = fmaf(v, wv.y, acc.y);
        acc.z = fmaf(v, wv.z, acc.z);
        acc.w = fmaf(v, wv.w, acc.w);
    }
    ((float4*)Y)[(long)row * (DM / 4) + tid] = acc;
}

// ============================================================
extern "C" void kernel_launch(void* const* d_in, const int* in_sizes, int n_in,
                              void* d_out, int out_size)
{
    const float* x     = (const float*)d_in[0];
    const float* W_enc = (const float*)d_in[1];
    const float* b_enc = (const float*)d_in[2];
    const float* W_dec = (const float*)d_in[3];
    const float* b_dec = (const float*)d_in[4];
    float* y = (float*)d_out;

    split_x_kernel<<<(TOK * DM) / (256 * 4), 256>>>(x);
    split_w_kernel<<<dim3(DH / 32, DM / 32), dim3(32, 8)>>>(W_enc);

    cudaFuncSetAttribute(encode_mma_kernel,
                         cudaFuncAttributeMaxDynamicSharedMemorySize, SMEM_DYN);
    dim3 ge(DH / BN, TOK / BM);   // (64, 32)
    encode_mma_kernel<<<ge, 256, SMEM_DYN>>>(b_enc);

    cudaFuncSetAttribute(topk_decode_kernel,
                         cudaFuncAttributeMaxDynamicSharedMemorySize, DH * 4);
    topk_decode_kernel<<<TOK, 256, DH * 4>>>(x, b_enc, W_dec, b_dec, y);
}

// round 11
// speedup vs baseline: 1.7296x; 1.7296x over previous
#include <cuda_runtime.h>
#include <cuda_bf16.h>
#include <cstdint>

#define TOK   4096
#define DH    16384
#define DM    1024
#define KSEL  64
#define CMAX  192
#define CBAND 448            // max compacted candidates for sort (<=512-pad)
#define RWIN  1.5e-2f

// ---- scratch (device globals; no runtime allocation) ----
__device__ float g_z[(long)TOK * DH];                        // 256 MB z~ (bf16-accurate)
__device__ __align__(16) __nv_bfloat16 g_Abf[(long)TOK * DM];
__device__ __align__(16) __nv_bfloat16 g_Bbf[(long)DH * DM]; // W_enc^T bf16
__device__ __align__(16) float         g_WT [(long)DH * DM]; // W_enc^T fp32
__device__ int   g_idx[TOK * KSEL];
__device__ float g_val[TOK * KSEL];
__device__ int   g_cnt[TOK];

// ============================================================
// helpers
// ============================================================
__device__ __forceinline__ uint32_t smem_u32(const void* p) {
    uint32_t a;
    asm("{ .reg .u64 t; cvta.to.shared.u64 t, %1; cvt.u32.u64 %0, t; }"
        : "=r"(a) : "l"(p));
    return a;
}
#define SWZ128(o) ((o) ^ (((o) >> 3) & 0x70))

#define CPASYNC16(dst, src) \
    asm volatile("cp.async.cg.shared.global [%0], [%1], 16;" \
                 :: "r"(dst), "l"(src) : "memory")
#define CP_COMMIT() asm volatile("cp.async.commit_group;" ::: "memory")

#define MMA16816(c, a, b0, b1) \
    asm volatile("mma.sync.aligned.m16n8k16.row.col.f32.bf16.bf16.f32 " \
        "{%0,%1,%2,%3}, {%4,%5,%6,%7}, {%8,%9}, {%0,%1,%2,%3};" \
        : "+f"((c)[0]), "+f"((c)[1]), "+f"((c)[2]), "+f"((c)[3]) \
        : "r"((a)[0]), "r"((a)[1]), "r"((a)[2]), "r"((a)[3]), "r"(b0), "r"(b1))

#define LDMATX4(r, ad) \
    asm volatile("ldmatrix.sync.aligned.m8n8.x4.shared.b16 {%0,%1,%2,%3}, [%4];" \
        : "=r"((r)[0]), "=r"((r)[1]), "=r"((r)[2]), "=r"((r)[3]) : "r"(ad))

// ---- double-float exact-ish dot (ranking only) ----
__device__ __forceinline__ void two_sum(float a, float b, float& s, float& e) {
    s = a + b;
    float bv = s - a;
    e = (a - (s - bv)) + (b - bv);
}
__device__ __forceinline__ double df_dot_warp(const float* __restrict__ x,
                                              const float* __restrict__ w,
                                              int lane) {
    float hi = 0.f, lo = 0.f;
    for (int k = lane; k < DM; k += 32) {
        float xv = x[k], wv = w[k];
        float p  = xv * wv;
        float pe = fmaf(xv, wv, -p);
        float s, e;
        two_sum(hi, p, s, e);
        lo += e + pe;
        hi = s;
    }
#pragma unroll
    for (int off = 16; off; off >>= 1) {
        float h2 = __shfl_down_sync(0xFFFFFFFFu, hi, off);
        float l2 = __shfl_down_sync(0xFFFFFFFFu, lo, off);
        float s, e;
        two_sum(hi, h2, s, e);
        lo = lo + l2 + e;
        hi = s;
    }
    return (double)hi + (double)lo;     // lane 0
}
// ---- plain fp32 dot (value recompute) ----
__device__ __forceinline__ float fp32_dot_warp(const float* __restrict__ x,
                                               const float* __restrict__ w,
                                               int lane) {
    float acc = 0.f;
    for (int k = lane; k < DM; k += 32) acc = fmaf(x[k], w[k], acc);
#pragma unroll
    for (int off = 16; off; off >>= 1)
        acc += __shfl_down_sync(0xFFFFFFFFu, acc, off);
    return acc;                          // lane 0
}

// ============================================================
// Prepass 1: x -> bf16
// ============================================================
__global__ __launch_bounds__(256) void split_x_kernel(const float* __restrict__ x)
{
    long i = (long)blockIdx.x * 256 + threadIdx.x;
    float4 v = ((const float4*)x)[i];
    __nv_bfloat16 h[4];
    h[0] = __float2bfloat16(v.x); h[1] = __float2bfloat16(v.y);
    h[2] = __float2bfloat16(v.z); h[3] = __float2bfloat16(v.w);
    ((uint2*)g_Abf)[i] = *(uint2*)h;
}

// ============================================================
// Prepass 2: transpose W_enc [DM,DH] -> [DH,DM] fp32 + bf16
// ============================================================
__global__ __launch_bounds__(256) void split_w_kernel(const float* __restrict__ W)
{
    __shared__ float s[32][33];
    const int n0 = blockIdx.x * 32, k0 = blockIdx.y * 32;
    const int tx = threadIdx.x, ty = threadIdx.y;
#pragma unroll
    for (int i = 0; i < 4; i++)
        s[ty + 8 * i][tx] = W[(long)(k0 + ty + 8 * i) * DH + n0 + tx];
    __syncthreads();
#pragma unroll
    for (int i = 0; i < 4; i++) {
        const int n = n0 + ty + 8 * i, k = k0 + tx;
        const float f = s[tx][ty + 8 * i];
        g_WT [(long)n * DM + k] = f;
        g_Bbf[(long)n * DM + k] = __float2bfloat16(f);
    }
}

// ============================================================
// Encode GEMM: bf16 mma.sync (HMMA) — unchanged from R9.
// ============================================================
#define BM 128
#define BN 256
#define BKG 64
#define ASTG 16384
#define STAGE 49152
#define NSTG 3
#define SMEM_DYN (NSTG * STAGE)

__global__ __launch_bounds__(256, 1) void encode_mma_kernel(const float* __restrict__ bias)
{
    extern __shared__ __align__(1024) char smem[];
    const uint32_t smb = smem_u32(smem);
    const int tid = threadIdx.x, lane = tid & 31, wid = tid >> 5;
    const int wm = wid >> 2, wn = wid & 3;
    const int m0 = blockIdx.y * BM, n0 = blockIdx.x * BN;

    int arow[4], bro[8];
    uint32_t asw[4], bsw[8];
    long asrc[4], bsrc[8];
#pragma unroll
    for (int i = 0; i < 4; i++) {
        int c = tid + 256 * i;
        arow[i] = c >> 3;
        int ch = c & 7;
        asw[i] = SWZ128((uint32_t)(arow[i] * 128 + ch * 16));
        asrc[i] = (long)(m0 + arow[i]) * DM + ch * 8;
    }
#pragma unroll
    for (int i = 0; i < 8; i++) {
        int c = tid + 256 * i;
        bro[i] = c >> 3;
        int ch = c & 7;
        bsw[i] = SWZ128((uint32_t)(bro[i] * 128 + ch * 16));
        bsrc[i] = (long)(n0 + bro[i]) * DM + ch * 8;
    }

    const int rowA = wm * 64 + (lane & 7) + ((lane >> 3) & 1) * 8;
    const int kbA  = ((lane >> 4) & 1) * 16;
    const int rowB = wn * 64 + (lane & 7) + ((lane >> 4) & 1) * 8;
    const int kbB  = ((lane >> 3) & 1) * 16;

    float acc[4][8][4];
#pragma unroll
    for (int m = 0; m < 4; m++)
#pragma unroll
        for (int n = 0; n < 8; n++)
#pragma unroll
            for (int r = 0; r < 4; r++) acc[m][n][r] = 0.f;

    auto issue = [&](int k0, int s) {
        const uint32_t As = smb + s * STAGE;
        const uint32_t Bs = As + ASTG;
#pragma unroll
        for (int i = 0; i < 4; i++)
            CPASYNC16(As + asw[i], (const char*)(g_Abf + asrc[i] + k0));
#pragma unroll
        for (int i = 0; i < 8; i++)
            CPASYNC16(Bs + bsw[i], (const char*)(g_Bbf + bsrc[i] + k0));
    };

    auto compute = [&](int s) {
        const uint32_t As = smb + s * STAGE;
        const uint32_t Bs = As + ASTG;
#pragma unroll
        for (int ks = 0; ks < 4; ks++) {
            uint32_t a[4][4], bq[4][4];
#pragma unroll
            for (int mt = 0; mt < 4; mt++) {
                uint32_t off = (uint32_t)((rowA + mt * 16) * 128 + ks * 32 + kbA);
                LDMATX4(a[mt], As + SWZ128(off));
            }
#pragma unroll
            for (int j = 0; j < 4; j++) {
                uint32_t off = (uint32_t)((rowB + j * 16) * 128 + ks * 32 + kbB);
                LDMATX4(bq[j], Bs + SWZ128(off));
            }
#pragma unroll
            for (int mt = 0; mt < 4; mt++)
#pragma unroll
                for (int j = 0; j < 4; j++) {
                    MMA16816(acc[mt][2 * j],     a[mt], bq[j][0], bq[j][1]);
                    MMA16816(acc[mt][2 * j + 1], a[mt], bq[j][2], bq[j][3]);
                }
        }
    };

    issue(0, 0);   CP_COMMIT();
    issue(64, 1);  CP_COMMIT();

    const int NIT = DM / BKG;
    for (int i = 0; i < NIT; i++) {
        if (i < NIT - 2) asm volatile("cp.async.wait_group 1;" ::: "memory");
        else             asm volatile("cp.async.wait_group 0;" ::: "memory");
        __syncthreads();
        compute(i % NSTG);
        if (i + 2 < NIT) {
            issue((i + 2) * BKG, (i + 2) % NSTG);
            CP_COMMIT();
        }
    }

    const int r0  = m0 + wm * 64 + (lane >> 2);
    const int c0  = n0 + wn * 64 + (lane & 3) * 2;
#pragma unroll
    for (int nt = 0; nt < 8; nt++) {
        const int col = c0 + nt * 8;
        const float2 bv = *(const float2*)&bias[col];
#pragma unroll
        for (int mt = 0; mt < 4; mt++) {
            const int r = r0 + mt * 16;
            float2 o0, o1;
            o0.x = fmaxf(acc[mt][nt][0] + bv.x, 0.f);
            o0.y = fmaxf(acc[mt][nt][1] + bv.y, 0.f);
            o1.x = fmaxf(acc[mt][nt][2] + bv.x, 0.f);
            o1.y = fmaxf(acc[mt][nt][3] + bv.y, 0.f);
            *(float2*)&g_z[(long)r * DH + col]       = o0;
            *(float2*)&g_z[(long)(r + 8) * DH + col] = o1;
        }
    }
}

// ============================================================
// TopK: moment-guided threshold + bitonic rank-64 + df window.
// All sweeps conflict-free (sm[i*256+tid]); order-free compaction
// (output ordering is irrelevant: y is a sum over the set).
// ============================================================
__global__ __launch_bounds__(256) void topk_kernel(
    const float* __restrict__ X,
    const float* __restrict__ benc)
{
    extern __shared__ unsigned sm[];   // 64 KB row
    __shared__ unsigned long long s_key[512];
    __shared__ int    s_cidx[CMAX];
    __shared__ double s_cval[CMAX];
    __shared__ float  s_p1[8], s_p2[8];
    __shared__ int    s_scan[256];     // fallback only
    __shared__ int    s_red, s_na, s_nc;
    __shared__ float  s_t;

    const int row = blockIdx.x;
    const int tid = threadIdx.x;
    const int wid = tid >> 5, lane = tid & 31;
    const float* xr = X + (long)row * DM;

    // ---- stage row + moments (free) ----
    {
        const uint4* z4 = (const uint4*)(g_z + (long)row * DH);
        uint4* s4 = (uint4*)sm;
        float sum = 0.f, ss = 0.f;
        for (int i = tid; i < DH / 4; i += 256) {
            uint4 u = z4[i];
            s4[i] = u;
            float a = __uint_as_float(u.x), b = __uint_as_float(u.y);
            float c = __uint_as_float(u.z), d = __uint_as_float(u.w);
            sum += (a + b) + (c + d);
            ss  += (a * a + b * b) + (c * c + d * d);
        }
#pragma unroll
        for (int o = 16; o; o >>= 1) {
            sum += __shfl_xor_sync(0xFFFFFFFFu, sum, o);
            ss  += __shfl_xor_sync(0xFFFFFFFFu, ss,  o);
        }
        if (lane == 0) { s_p1[wid] = sum; s_p2[wid] = ss; }
        __syncthreads();
        if (tid == 0) {
            float S = 0.f, S2 = 0.f;
#pragma unroll
            for (int w = 0; w < 8; w++) { S += s_p1[w]; S2 += s_p2[w]; }
            const float mu = S / DH;
            const float var = fmaxf(S2 / DH - mu * mu, 0.f);
            s_t = mu + 3.0f * sqrtf(var);
        }
        __syncthreads();
    }

    // ---- threshold iteration: find t with 64 <= count(>=t) <= CBAND ----
    float t = s_t;
    int c = -1;
    bool ok = false;
    for (int it = 0; it < 24; ++it) {
        if (!(t > 4.f * RWIN)) break;        // degenerate -> fallback
        const unsigned tb = __float_as_uint(t);
        if (tid == 0) s_red = 0;
        __syncthreads();
        int cc = 0;
#pragma unroll 8
        for (int i = 0; i < DH / 256; i++)
            cc += (sm[i * 256 + tid] >= tb) ? 1 : 0;
#pragma unroll
        for (int o = 16; o; o >>= 1) cc += __shfl_xor_sync(0xFFFFFFFFu, cc, o);
        if (lane == 0) atomicAdd(&s_red, cc);
        __syncthreads();
        c = s_red;
        __syncthreads();
        if (c >= KSEL && c <= CBAND) { ok = true; break; }
        t = (c < KSEL) ? t * 0.85f : t * 1.12f;
    }

    bool fast = false;

    if (ok) {
        // ---- compact candidates (any order) as 64-bit keys ----
        if (tid == 0) s_nc = 0;
        __syncthreads();
        const unsigned tb = __float_as_uint(t);
        for (int i = 0; i < DH / 256; i++) {
            const int gi = i * 256 + tid;
            const unsigned v = sm[gi];
            if (v >= tb) {
                int p = atomicAdd(&s_nc, 1);
                s_key[p] = ((unsigned long long)v << 32)
                         | (unsigned)(0xFFFFFFFFu - (unsigned)gi);
            }
        }
        __syncthreads();
        const int cc0 = s_nc;                 // in [64, CBAND]
        for (int p = tid; p < 512; p += 256)
            if (p >= cc0) s_key[p] = 0ull;
        __syncthreads();

        // ---- bitonic sort 512 keys, descending ----
        for (int k = 2; k <= 512; k <<= 1) {
            for (int j = k >> 1; j; j >>= 1) {
#pragma unroll
                for (int rr = 0; rr < 2; rr++) {
                    const int i2 = tid + 256 * rr;
                    const int p = i2 ^ j;
                    if (p > i2) {
                        unsigned long long a = s_key[i2], b = s_key[p];
                        const bool up = ((i2 & k) == 0);
                        if (up ? (a < b) : (a > b)) { s_key[i2] = b; s_key[p] = a; }
                    }
                }
                __syncthreads();
            }
        }

        const unsigned t64b = (unsigned)(s_key[63] >> 32);   // exact rank-64 of z~
        const float tf = __uint_as_float(t64b);

        if (tf > 2.0f * RWIN) {
            const unsigned hib = __float_as_uint(tf + RWIN);
            const unsigned lob = __float_as_uint(tf - RWIN);
            if (tid == 0) { s_na = 0; s_nc = 0; }
            __syncthreads();
            // single sweep: A-set (certain) + window candidates
            for (int i = 0; i < DH / 256; i++) {
                const int gi = i * 256 + tid;
                const unsigned v = sm[gi];
                if (v > hib) {
                    int p = atomicAdd(&s_na, 1);
                    g_idx[row * KSEL + p] = gi;
                } else if (v >= lob) {
                    int p = atomicAdd(&s_nc, 1);
                    if (p < CMAX) s_cidx[p] = gi;
                }
            }
            __syncthreads();
            const int cA = s_na, cC = s_nc;   // cA <= 63 by rank-64 def
            if (cC <= CMAX) {
                // df-exact values for candidates (warp per candidate)
                for (int c2 = wid; c2 < cC; c2 += 8) {
                    const int fi = s_cidx[c2];
                    double d = df_dot_warp(xr, g_WT + (long)fi * DM, lane);
                    if (lane == 0) {
                        d += (double)benc[fi];
                        s_cval[c2] = d > 0.0 ? d : 0.0;
                    }
                }
                __syncthreads();
                // exact ranking (value desc, index asc); keep top need
                const int need = KSEL - cA;
                for (int c2 = tid; c2 < cC; c2 += 256) {
                    const double v = s_cval[c2];
                    const int fi = s_cidx[c2];
                    int rank = 0;
                    for (int c3 = 0; c3 < cC; c3++) {
                        const double u = s_cval[c3];
                        if (u > v || (u == v && s_cidx[c3] < fi)) rank++;
                    }
                    if (rank < need) g_idx[row * KSEL + cA + rank] = fi;
                }
                __syncthreads();
                // fp32 recompute of ALL selected values
                for (int j = wid; j < KSEL; j += 8) {
                    const int fi = g_idx[row * KSEL + j];
                    float d = fp32_dot_warp(xr, g_WT + (long)fi * DM, lane);
                    if (lane == 0) {
                        d += benc[fi];
                        g_val[row * KSEL + j] = fmaxf(d, 0.f);
                    }
                }
                if (tid == 0) g_cnt[row] = KSEL;
                fast = true;
            }
            __syncthreads();
        }
    }

    if (!fast) {
        // ---- legacy fallback: exact binary search + ordered selection ----
        const int base = tid * (DH / 256);
        unsigned lo = 0u, hi = 0x7F800000u;
        while (lo < hi) {
            unsigned mid = lo + ((hi - lo + 1) >> 1);
            if (tid == 0) s_red = 0;
            __syncthreads();
            int cc = 0;
#pragma unroll 8
            for (int i = 0; i < DH / 256; i++)
                cc += (sm[i * 256 + tid] >= mid) ? 1 : 0;
#pragma unroll
            for (int o = 16; o; o >>= 1) cc += __shfl_xor_sync(0xFFFFFFFFu, cc, o);
            if (lane == 0) atomicAdd(&s_red, cc);
            __syncthreads();
            int cnt = s_red;
            if (cnt >= KSEL) lo = mid; else hi = mid - 1;
            __syncthreads();
        }
        const unsigned tt = lo;

        int ng = 0;
#pragma unroll 8
        for (int i = 0; i < DH / 256; i++) ng += (sm[base + i] > tt) ? 1 : 0;
        s_scan[tid] = ng;
        __syncthreads();
        for (int off = 1; off < 256; off <<= 1) {
            int v = (tid >= off) ? s_scan[tid - off] : 0;
            __syncthreads();
            s_scan[tid] += v;
            __syncthreads();
        }
        const int c_gt = s_scan[255];
        {
            int w = s_scan[tid] - ng;
            for (int i = 0; i < DH / 256; i++) {
                unsigned v = sm[base + i];
                if (v > tt) {
                    g_idx[row * KSEL + w] = base + i;
                    g_val[row * KSEL + w] = __uint_as_float(v);
                    w++;
                }
            }
        }
        int cnt_final = c_gt;
        if (tt != 0u) {
            __syncthreads();
            int ne = 0;
#pragma unroll 8
            for (int i = 0; i < DH / 256; i++) ne += (sm[base + i] == tt) ? 1 : 0;
            s_scan[tid] = ne;
            __syncthreads();
            for (int off = 1; off < 256; off <<= 1) {
                int v = (tid >= off) ? s_scan[tid - off] : 0;
                __syncthreads();
                s_scan[tid] += v;
                __syncthreads();
            }
            int pos = c_gt + s_scan[tid] - ne;
            for (int i = 0; i < DH / 256; i++) {
                if (sm[base + i] == tt) {
                    if (pos < KSEL) {
                        g_idx[row * KSEL + pos] = base + i;
                        g_val[row * KSEL + pos] = __uint_as_float(tt);
                    }
                    pos++;
                }
            }
            cnt_final = KSEL;
        }
        if (tid == 0) g_cnt[row] = cnt_final;
    }
}

// ============================================================
// Decode: y[row,:] = b_dec + sum_j val_j * W_dec[idx_j, :]
// ============================================================
__global__ __launch_bounds__(256) void decode_kernel(
    const float* __restrict__ Wd,
    const float* __restrict__ bd,
    float* __restrict__ Y)
{
    __shared__ float s_val[KSEL];
    __shared__ int   s_idx[KSEL];
    const int row = blockIdx.x;
    const int tid = threadIdx.x;
    const int cnt = g_cnt[row];

    if (tid < KSEL) {
        s_idx[tid] = (tid < cnt) ? g_idx[row * KSEL + tid] : 0;
        s_val[tid] = (tid < cnt) ? g_val[row * KSEL + tid] : 0.f;
    }
    __syncthreads();

    float4 acc = ((const float4*)bd)[tid];
#pragma unroll 4
    for (int j = 0; j < cnt; j++) {
        const float v = s_val[j];
        const float4 wv = ((const float4*)(Wd + (long)s_idx[j] * DM))[tid];
        acc.x = fmaf(v, wv.x, acc.x);
        acc.y = fmaf(v, wv.y, acc.y);
        acc.z = fmaf(v, wv.z, acc.z);
        acc.w = fmaf(v, wv.w, acc.w);
    }
    ((float4*)Y)[(long)row * (DM / 4) + tid] = acc;
}

// ============================================================
extern "C" void kernel_launch(void* const* d_in, const int* in_sizes, int n_in,
                              void* d_out, int out_size)
{
    const float* x     = (const float*)d_in[0];
    const float* W_enc = (const float*)d_in[1];
    const float* b_enc = (const float*)d_in[2];
    const float* W_dec = (const float*)d_in[3];
    const float* b_dec = (const float*)d_in[4];
    float* y = (float*)d_out;

    split_x_kernel<<<(TOK * DM) / (256 * 4), 256>>>(x);
    split_w_kernel<<<dim3(DH / 32, DM / 32), dim3(32, 8)>>>(W_enc);

    cudaFuncSetAttribute(encode_mma_kernel,
                         cudaFuncAttributeMaxDynamicSharedMemorySize, SMEM_DYN);
    dim3 ge(DH / BN, TOK / BM);   // (64, 32)
    encode_mma_kernel<<<ge, 256, SMEM_DYN>>>(b_enc);

    cudaFuncSetAttribute(topk_kernel,
                         cudaFuncAttributeMaxDynamicSharedMemorySize, DH * 4);
    topk_kernel<<<TOK, 256, DH * 4>>>(x, b_enc);

    decode_kernel<<<TOK, 256>>>(W_dec, b_dec, y);
}

// round 12
// speedup vs baseline: 2.2067x; 1.2758x over previous
#include <cuda_runtime.h>
#include <cuda_bf16.h>
#include <cstdint>

#define TOK   4096
#define DH    16384
#define DM    1024
#define KSEL  64
#define CMAX  192
#define CBAND 448            // max compacted candidates for sort (<=512-pad)
#define RWIN  1.5e-2f

// ---- scratch (device globals; no runtime allocation) ----
__device__ float g_z[(long)TOK * DH];                        // 256 MB z~ (bf16-accurate)
__device__ __align__(16) __nv_bfloat16 g_Abf[(long)TOK * DM];
__device__ __align__(16) __nv_bfloat16 g_Bbf[(long)DH * DM]; // W_enc^T bf16
__device__ __align__(16) float         g_WT [(long)DH * DM]; // W_enc^T fp32
__device__ int   g_idx[TOK * KSEL];
__device__ float g_val[TOK * KSEL];
__device__ int   g_cnt[TOK];

// ============================================================
// helpers
// ============================================================
__device__ __forceinline__ uint32_t smem_u32(const void* p) {
    uint32_t a;
    asm("{ .reg .u64 t; cvta.to.shared.u64 t, %1; cvt.u32.u64 %0, t; }"
        : "=r"(a) : "l"(p));
    return a;
}
#define SWZ128(o) ((o) ^ (((o) >> 3) & 0x70))

#define CPASYNC16(dst, src) \
    asm volatile("cp.async.cg.shared.global [%0], [%1], 16;" \
                 :: "r"(dst), "l"(src) : "memory")
#define CP_COMMIT() asm volatile("cp.async.commit_group;" ::: "memory")

#define MMA16816(c, a, b0, b1) \
    asm volatile("mma.sync.aligned.m16n8k16.row.col.f32.bf16.bf16.f32 " \
        "{%0,%1,%2,%3}, {%4,%5,%6,%7}, {%8,%9}, {%0,%1,%2,%3};" \
        : "+f"((c)[0]), "+f"((c)[1]), "+f"((c)[2]), "+f"((c)[3]) \
        : "r"((a)[0]), "r"((a)[1]), "r"((a)[2]), "r"((a)[3]), "r"(b0), "r"(b1))

#define LDMATX4(r, ad) \
    asm volatile("ldmatrix.sync.aligned.m8n8.x4.shared.b16 {%0,%1,%2,%3}, [%4];" \
        : "=r"((r)[0]), "=r"((r)[1]), "=r"((r)[2]), "=r"((r)[3]) : "r"(ad))

// ---- double-float exact-ish dot (ranking only) ----
__device__ __forceinline__ void two_sum(float a, float b, float& s, float& e) {
    s = a + b;
    float bv = s - a;
    e = (a - (s - bv)) + (b - bv);
}
__device__ __forceinline__ double df_dot_warp(const float* __restrict__ x,
                                              const float* __restrict__ w,
                                              int lane) {
    float hi = 0.f, lo = 0.f;
    for (int k = lane; k < DM; k += 32) {
        float xv = x[k], wv = w[k];
        float p  = xv * wv;
        float pe = fmaf(xv, wv, -p);
        float s, e;
        two_sum(hi, p, s, e);
        lo += e + pe;
        hi = s;
    }
#pragma unroll
    for (int off = 16; off; off >>= 1) {
        float h2 = __shfl_down_sync(0xFFFFFFFFu, hi, off);
        float l2 = __shfl_down_sync(0xFFFFFFFFu, lo, off);
        float s, e;
        two_sum(hi, h2, s, e);
        lo = lo + l2 + e;
        hi = s;
    }
    return (double)hi + (double)lo;     // lane 0
}
// ---- plain fp32 dot (value recompute) ----
__device__ __forceinline__ float fp32_dot_warp(const float* __restrict__ x,
                                               const float* __restrict__ w,
                                               int lane) {
    float acc = 0.f;
    for (int k = lane; k < DM; k += 32) acc = fmaf(x[k], w[k], acc);
#pragma unroll
    for (int off = 16; off; off >>= 1)
        acc += __shfl_down_sync(0xFFFFFFFFu, acc, off);
    return acc;                          // lane 0
}

// ============================================================
// Prepass 1: x -> bf16
// ============================================================
__global__ __launch_bounds__(256) void split_x_kernel(const float* __restrict__ x)
{
    long i = (long)blockIdx.x * 256 + threadIdx.x;
    float4 v = ((const float4*)x)[i];
    __nv_bfloat16 h[4];
    h[0] = __float2bfloat16(v.x); h[1] = __float2bfloat16(v.y);
    h[2] = __float2bfloat16(v.z); h[3] = __float2bfloat16(v.w);
    ((uint2*)g_Abf)[i] = *(uint2*)h;
}

// ============================================================
// Prepass 2: transpose W_enc [DM,DH] -> [DH,DM] fp32 + bf16
// ============================================================
__global__ __launch_bounds__(256) void split_w_kernel(const float* __restrict__ W)
{
    __shared__ float s[32][33];
    const int n0 = blockIdx.x * 32, k0 = blockIdx.y * 32;
    const int tx = threadIdx.x, ty = threadIdx.y;
#pragma unroll
    for (int i = 0; i < 4; i++)
        s[ty + 8 * i][tx] = W[(long)(k0 + ty + 8 * i) * DH + n0 + tx];
    __syncthreads();
#pragma unroll
    for (int i = 0; i < 4; i++) {
        const int n = n0 + ty + 8 * i, k = k0 + tx;
        const float f = s[tx][ty + 8 * i];
        g_WT [(long)n * DM + k] = f;
        g_Bbf[(long)n * DM + k] = __float2bfloat16(f);
    }
}

// ============================================================
// Encode GEMM: bf16 mma.sync (HMMA) — unchanged from R9.
// ============================================================
#define BM 128
#define BN 256
#define BKG 64
#define ASTG 16384
#define STAGE 49152
#define NSTG 3
#define SMEM_DYN (NSTG * STAGE)

__global__ __launch_bounds__(256, 1) void encode_mma_kernel(const float* __restrict__ bias)
{
    extern __shared__ __align__(1024) char smem[];
    const uint32_t smb = smem_u32(smem);
    const int tid = threadIdx.x, lane = tid & 31, wid = tid >> 5;
    const int wm = wid >> 2, wn = wid & 3;
    const int m0 = blockIdx.y * BM, n0 = blockIdx.x * BN;

    int arow[4], bro[8];
    uint32_t asw[4], bsw[8];
    long asrc[4], bsrc[8];
#pragma unroll
    for (int i = 0; i < 4; i++) {
        int c = tid + 256 * i;
        arow[i] = c >> 3;
        int ch = c & 7;
        asw[i] = SWZ128((uint32_t)(arow[i] * 128 + ch * 16));
        asrc[i] = (long)(m0 + arow[i]) * DM + ch * 8;
    }
#pragma unroll
    for (int i = 0; i < 8; i++) {
        int c = tid + 256 * i;
        bro[i] = c >> 3;
        int ch = c & 7;
        bsw[i] = SWZ128((uint32_t)(bro[i] * 128 + ch * 16));
        bsrc[i] = (long)(n0 + bro[i]) * DM + ch * 8;
    }

    const int rowA = wm * 64 + (lane & 7) + ((lane >> 3) & 1) * 8;
    const int kbA  = ((lane >> 4) & 1) * 16;
    const int rowB = wn * 64 + (lane & 7) + ((lane >> 4) & 1) * 8;
    const int kbB  = ((lane >> 3) & 1) * 16;

    float acc[4][8][4];
#pragma unroll
    for (int m = 0; m < 4; m++)
#pragma unroll
        for (int n = 0; n < 8; n++)
#pragma unroll
            for (int r = 0; r < 4; r++) acc[m][n][r] = 0.f;

    auto issue = [&](int k0, int s) {
        const uint32_t As = smb + s * STAGE;
        const uint32_t Bs = As + ASTG;
#pragma unroll
        for (int i = 0; i < 4; i++)
            CPASYNC16(As + asw[i], (const char*)(g_Abf + asrc[i] + k0));
#pragma unroll
        for (int i = 0; i < 8; i++)
            CPASYNC16(Bs + bsw[i], (const char*)(g_Bbf + bsrc[i] + k0));
    };

    auto compute = [&](int s) {
        const uint32_t As = smb + s * STAGE;
        const uint32_t Bs = As + ASTG;
#pragma unroll
        for (int ks = 0; ks < 4; ks++) {
            uint32_t a[4][4], bq[4][4];
#pragma unroll
            for (int mt = 0; mt < 4; mt++) {
                uint32_t off = (uint32_t)((rowA + mt * 16) * 128 + ks * 32 + kbA);
                LDMATX4(a[mt], As + SWZ128(off));
            }
#pragma unroll
            for (int j = 0; j < 4; j++) {
                uint32_t off = (uint32_t)((rowB + j * 16) * 128 + ks * 32 + kbB);
                LDMATX4(bq[j], Bs + SWZ128(off));
            }
#pragma unroll
            for (int mt = 0; mt < 4; mt++)
#pragma unroll
                for (int j = 0; j < 4; j++) {
                    MMA16816(acc[mt][2 * j],     a[mt], bq[j][0], bq[j][1]);
                    MMA16816(acc[mt][2 * j + 1], a[mt], bq[j][2], bq[j][3]);
                }
        }
    };

    issue(0, 0);   CP_COMMIT();
    issue(64, 1);  CP_COMMIT();

    const int NIT = DM / BKG;
    for (int i = 0; i < NIT; i++) {
        if (i < NIT - 2) asm volatile("cp.async.wait_group 1;" ::: "memory");
        else             asm volatile("cp.async.wait_group 0;" ::: "memory");
        __syncthreads();
        compute(i % NSTG);
        if (i + 2 < NIT) {
            issue((i + 2) * BKG, (i + 2) % NSTG);
            CP_COMMIT();
        }
    }

    const int r0  = m0 + wm * 64 + (lane >> 2);
    const int c0  = n0 + wn * 64 + (lane & 3) * 2;
#pragma unroll
    for (int nt = 0; nt < 8; nt++) {
        const int col = c0 + nt * 8;
        const float2 bv = *(const float2*)&bias[col];
#pragma unroll
        for (int mt = 0; mt < 4; mt++) {
            const int r = r0 + mt * 16;
            float2 o0, o1;
            o0.x = fmaxf(acc[mt][nt][0] + bv.x, 0.f);
            o0.y = fmaxf(acc[mt][nt][1] + bv.y, 0.f);
            o1.x = fmaxf(acc[mt][nt][2] + bv.x, 0.f);
            o1.y = fmaxf(acc[mt][nt][3] + bv.y, 0.f);
            *(float2*)&g_z[(long)r * DH + col]       = o0;
            *(float2*)&g_z[(long)(r + 8) * DH + col] = o1;
        }
    }
}

// ============================================================
// TopK: 16-bit quantized staging (32 KB smem -> 5 CTA/SM),
// moment-guided threshold + bitonic rank-64 + widened df window.
// fp32 z bits never needed: all selected values are recomputed.
// ============================================================
__global__ __launch_bounds__(256) void topk_kernel(
    const float* __restrict__ X,
    const float* __restrict__ benc)
{
    extern __shared__ unsigned smq[];   // 32 KB: DH quantized 16-bit, 2 per uint
    __shared__ float  s_x[DM];          // 4 KB x row
    __shared__ unsigned s_key[512];
    __shared__ int    s_cidx[CMAX];
    __shared__ double s_cval[CMAX];
    __shared__ float  s_p1[8], s_p2[8];
    __shared__ int    s_scan[256];      // fallback only
    __shared__ int    s_red, s_na, s_nc;
    __shared__ float  s_t;

    const int row = blockIdx.x;
    const int tid = threadIdx.x;
    const int wid = tid >> 5, lane = tid & 31;
    const float* xr = X + (long)row * DM;

    // ---- stage x row ----
    for (int k = tid; k < DM; k += 256) s_x[k] = xr[k];

    // ---- stage quantized row + moments ----
    {
        const uint4* z4 = (const uint4*)(g_z + (long)row * DH);
        float sum = 0.f, ss = 0.f;
        for (int i = tid; i < DH / 4; i += 256) {
            uint4 u = z4[i];
            float a = __uint_as_float(u.x), b = __uint_as_float(u.y);
            float c = __uint_as_float(u.z), d = __uint_as_float(u.w);
            sum += (a + b) + (c + d);
            ss  += (a * a + b * b) + (c * c + d * d);
            // pack 4 x 16-bit truncated (order-preserving for z >= 0)
            smq[2 * i]     = (u.x >> 16) | (u.y & 0xFFFF0000u);
            smq[2 * i + 1] = (u.z >> 16) | (u.w & 0xFFFF0000u);
        }
#pragma unroll
        for (int o = 16; o; o >>= 1) {
            sum += __shfl_xor_sync(0xFFFFFFFFu, sum, o);
            ss  += __shfl_xor_sync(0xFFFFFFFFu, ss,  o);
        }
        if (lane == 0) { s_p1[wid] = sum; s_p2[wid] = ss; }
        __syncthreads();
        if (tid == 0) {
            float S = 0.f, S2 = 0.f;
#pragma unroll
            for (int w = 0; w < 8; w++) { S += s_p1[w]; S2 += s_p2[w]; }
            const float mu = S / DH;
            const float var = fmaxf(S2 / DH - mu * mu, 0.f);
            s_t = mu + 3.0f * sqrtf(var);
        }
        __syncthreads();
    }

    // ---- threshold iteration on quantized values ----
    float t = s_t;
    unsigned tb16 = 0;
    bool ok = false;
    for (int it = 0; it < 24; ++it) {
        if (!(t > 4.f * RWIN)) break;
        const unsigned q16 = __float_as_uint(t) >> 16;
        if (tid == 0) s_red = 0;
        __syncthreads();
        int cc = 0;
#pragma unroll 8
        for (int i = 0; i < DH / 512; i++) {        // 32 packed uints/thread
            const unsigned u = smq[i * 256 + tid];
            cc += ((u & 0xFFFFu) >= q16) ? 1 : 0;
            cc += ((u >> 16)     >= q16) ? 1 : 0;
        }
#pragma unroll
        for (int o = 16; o; o >>= 1) cc += __shfl_xor_sync(0xFFFFFFFFu, cc, o);
        if (lane == 0) atomicAdd(&s_red, cc);
        __syncthreads();
        const int c = s_red;
        __syncthreads();
        if (c >= KSEL && c <= CBAND) { tb16 = q16; ok = true; break; }
        t = (c < KSEL) ? t * 0.85f : t * 1.12f;
    }

    bool fast = false;

    if (ok) {
        // ---- compact candidate values (order-free) ----
        if (tid == 0) s_nc = 0;
        __syncthreads();
        for (int i = 0; i < DH / 512; i++) {
            const unsigned u = smq[i * 256 + tid];
            const unsigned v0 = u & 0xFFFFu, v1 = u >> 16;
            if (v0 >= tb16) { int p = atomicAdd(&s_nc, 1); s_key[p] = v0; }
            if (v1 >= tb16) { int p = atomicAdd(&s_nc, 1); s_key[p] = v1; }
        }
        __syncthreads();
        const int cc0 = s_nc;                 // in [64, CBAND]
        for (int p = tid; p < 512; p += 256)
            if (p >= cc0) s_key[p] = 0u;
        __syncthreads();

        // ---- bitonic sort 512 values, descending ----
        for (int k = 2; k <= 512; k <<= 1) {
            for (int j = k >> 1; j; j >>= 1) {
#pragma unroll
                for (int rr = 0; rr < 2; rr++) {
                    const int i2 = tid + 256 * rr;
                    const int p = i2 ^ j;
                    if (p > i2) {
                        unsigned a = s_key[i2], b = s_key[p];
                        const bool up = ((i2 & k) == 0);
                        if (up ? (a < b) : (a > b)) { s_key[i2] = b; s_key[p] = a; }
                    }
                }
                __syncthreads();
            }
        }

        const unsigned h64 = s_key[63];       // quantized rank-64 of z~
        const float tf_lo = __uint_as_float(h64 << 16);
        const float qw = __uint_as_float((h64 + 1) << 16) - tf_lo;

        if (tf_lo > 2.0f * RWIN) {
            // window algebra: tf_lo <= t~ < tf_lo+qw  (t~ = exact rank-64 of z~)
            const unsigned hib16 = __float_as_uint(tf_lo + qw + RWIN) >> 16;
            const unsigned lob16 = __float_as_uint(tf_lo - RWIN) >> 16;
            if (tid == 0) { s_na = 0; s_nc = 0; }
            __syncthreads();
            for (int i = 0; i < DH / 512; i++) {
                const unsigned u = smq[i * 256 + tid];
                const int gi0 = (i * 256 + tid) * 2;
#pragma unroll
                for (int h = 0; h < 2; h++) {
                    const unsigned v = h ? (u >> 16) : (u & 0xFFFFu);
                    const int gi = gi0 + h;
                    if (v > hib16) {                 // certain: z~ > hib >= t~+RWIN
                        int p = atomicAdd(&s_na, 1);
                        g_idx[row * KSEL + p] = gi;
                    } else if (v >= lob16) {         // window candidate
                        int p = atomicAdd(&s_nc, 1);
                        if (p < CMAX) s_cidx[p] = gi;
                    }
                }
            }
            __syncthreads();
            const int cA = s_na, cC = s_nc;   // cA <= 63 by construction
            if (cC <= CMAX) {
                // df-exact values for candidates (warp per candidate)
                for (int c2 = wid; c2 < cC; c2 += 8) {
                    const int fi = s_cidx[c2];
                    double d = df_dot_warp(s_x, g_WT + (long)fi * DM, lane);
                    if (lane == 0) {
                        d += (double)benc[fi];
                        s_cval[c2] = d > 0.0 ? d : 0.0;
                    }
                }
                __syncthreads();
                // exact ranking (value desc, index asc); keep top need
                const int need = KSEL - cA;
                for (int c2 = tid; c2 < cC; c2 += 256) {
                    const double v = s_cval[c2];
                    const int fi = s_cidx[c2];
                    int rank = 0;
                    for (int c3 = 0; c3 < cC; c3++) {
                        const double u = s_cval[c3];
                        if (u > v || (u == v && s_cidx[c3] < fi)) rank++;
                    }
                    if (rank < need) g_idx[row * KSEL + cA + rank] = fi;
                }
                __syncthreads();
                // fp32 recompute of ALL selected values
                for (int j = wid; j < KSEL; j += 8) {
                    const int fi = g_idx[row * KSEL + j];
                    float d = fp32_dot_warp(s_x, g_WT + (long)fi * DM, lane);
                    if (lane == 0) {
                        d += benc[fi];
                        g_val[row * KSEL + j] = fmaxf(d, 0.f);
                    }
                }
                if (tid == 0) g_cnt[row] = KSEL;
                fast = true;
            }
            __syncthreads();
        }
    }

    if (!fast) {
        // ---- legacy fallback (degenerate rows): fp32 z from global ----
        const unsigned* zrow = (const unsigned*)(g_z + (long)row * DH);
        const int base = tid * (DH / 256);
        unsigned lo = 0u, hi = 0x7F800000u;
        while (lo < hi) {
            unsigned mid = lo + ((hi - lo + 1) >> 1);
            if (tid == 0) s_red = 0;
            __syncthreads();
            int cc = 0;
#pragma unroll 8
            for (int i = 0; i < DH / 256; i++)
                cc += (zrow[i * 256 + tid] >= mid) ? 1 : 0;
#pragma unroll
            for (int o = 16; o; o >>= 1) cc += __shfl_xor_sync(0xFFFFFFFFu, cc, o);
            if (lane == 0) atomicAdd(&s_red, cc);
            __syncthreads();
            int cnt = s_red;
            if (cnt >= KSEL) lo = mid; else hi = mid - 1;
            __syncthreads();
        }
        const unsigned tt = lo;

        int ng = 0;
#pragma unroll 8
        for (int i = 0; i < DH / 256; i++) ng += (zrow[base + i] > tt) ? 1 : 0;
        s_scan[tid] = ng;
        __syncthreads();
        for (int off = 1; off < 256; off <<= 1) {
            int v = (tid >= off) ? s_scan[tid - off] : 0;
            __syncthreads();
            s_scan[tid] += v;
            __syncthreads();
        }
        const int c_gt = s_scan[255];
        {
            int w = s_scan[tid] - ng;
            for (int i = 0; i < DH / 256; i++) {
                unsigned v = zrow[base + i];
                if (v > tt) {
                    g_idx[row * KSEL + w] = base + i;
                    g_val[row * KSEL + w] = __uint_as_float(v);
                    w++;
                }
            }
        }
        int cnt_final = c_gt;
        if (tt != 0u) {
            __syncthreads();
            int ne = 0;
#pragma unroll 8
            for (int i = 0; i < DH / 256; i++) ne += (zrow[base + i] == tt) ? 1 : 0;
            s_scan[tid] = ne;
            __syncthreads();
            for (int off = 1; off < 256; off <<= 1) {
                int v = (tid >= off) ? s_scan[tid - off] : 0;
                __syncthreads();
                s_scan[tid] += v;
                __syncthreads();
            }
            int pos = c_gt + s_scan[tid] - ne;
            for (int i = 0; i < DH / 256; i++) {
                if (zrow[base + i] == tt) {
                    if (pos < KSEL) {
                        g_idx[row * KSEL + pos] = base + i;
                        g_val[row * KSEL + pos] = __uint_as_float(tt);
                    }
                    pos++;
                }
            }
            cnt_final = KSEL;
        }
        if (tid == 0) g_cnt[row] = cnt_final;
    }
}

// ============================================================
// Decode: y[row,:] = b_dec + sum_j val_j * W_dec[idx_j, :]
// ============================================================
__global__ __launch_bounds__(256) void decode_kernel(
    const float* __restrict__ Wd,
    const float* __restrict__ bd,
    float* __restrict__ Y)
{
    __shared__ float s_val[KSEL];
    __shared__ int   s_idx[KSEL];
    const int row = blockIdx.x;
    const int tid = threadIdx.x;
    const int cnt = g_cnt[row];

    if (tid < KSEL) {
        s_idx[tid] = (tid < cnt) ? g_idx[row * KSEL + tid] : 0;
        s_val[tid] = (tid < cnt) ? g_val[row * KSEL + tid] : 0.f;
    }
    __syncthreads();

    float4 acc = ((const float4*)bd)[tid];
#pragma unroll 4
    for (int j = 0; j < cnt; j++) {
        const float v = s_val[j];
        const float4 wv = ((const float4*)(Wd + (long)s_idx[j] * DM))[tid];
        acc.x = fmaf(v, wv.x, acc.x);
        acc.y = fmaf(v, wv.y, acc.y);
        acc.z = fmaf(v, wv.z, acc.z);
        acc.w = fmaf(v, wv.w, acc.w);
    }
    ((float4*)Y)[(long)row * (DM / 4) + tid] = acc;
}

// ============================================================
extern "C" void kernel_launch(void* const* d_in, const int* in_sizes, int n_in,
                              void* d_out, int out_size)
{
    const float* x     = (const float*)d_in[0];
    const float* W_enc = (const float*)d_in[1];
    const float* b_enc = (const float*)d_in[2];
    const float* W_dec = (const float*)d_in[3];
    const float* b_dec = (const float*)d_in[4];
    float* y = (float*)d_out;

    split_x_kernel<<<(TOK * DM) / (256 * 4), 256>>>(x);
    split_w_kernel<<<dim3(DH / 32, DM / 32), dim3(32, 8)>>>(W_enc);

    cudaFuncSetAttribute(encode_mma_kernel,
                         cudaFuncAttributeMaxDynamicSharedMemorySize, SMEM_DYN);
    dim3 ge(DH / BN, TOK / BM);   // (64, 32)
    encode_mma_kernel<<<ge, 256, SMEM_DYN>>>(b_enc);

    cudaFuncSetAttribute(topk_kernel,
                         cudaFuncAttributeMaxDynamicSharedMemorySize, DH * 2);
    topk_kernel<<<TOK, 256, DH * 2>>>(x, b_enc);

    decode_kernel<<<TOK, 256>>>(W_dec, b_dec, y);
}

// round 13
// speedup vs baseline: 2.3096x; 1.0466x over previous
#include <cuda_runtime.h>
#include <cuda_bf16.h>
#include <cstdint>

#define TOK   4096
#define DH    16384
#define DM    1024
#define KSEL  64
#define CMAX  192
#define CBAND 448
#define RWIN  1.5e-2f

// ---- scratch (device globals; no runtime allocation) ----
__device__ __align__(16) unsigned short g_zq[(long)TOK * DH];  // 128 MB quantized z
__device__ __align__(16) __nv_bfloat16 g_Abf[(long)TOK * DM];
__device__ __align__(16) __nv_bfloat16 g_Bbf[(long)DH * DM];   // W_enc^T bf16
__device__ __align__(16) float         g_WT [(long)DH * DM];   // W_enc^T fp32

// ============================================================
// helpers
// ============================================================
__device__ __forceinline__ uint32_t smem_u32(const void* p) {
    uint32_t a;
    asm("{ .reg .u64 t; cvta.to.shared.u64 t, %1; cvt.u32.u64 %0, t; }"
        : "=r"(a) : "l"(p));
    return a;
}
#define SWZ128(o) ((o) ^ (((o) >> 3) & 0x70))

#define CPASYNC16(dst, src) \
    asm volatile("cp.async.cg.shared.global [%0], [%1], 16;" \
                 :: "r"(dst), "l"(src) : "memory")
#define CP_COMMIT() asm volatile("cp.async.commit_group;" ::: "memory")

#define MMA16816(c, a, b0, b1) \
    asm volatile("mma.sync.aligned.m16n8k16.row.col.f32.bf16.bf16.f32 " \
        "{%0,%1,%2,%3}, {%4,%5,%6,%7}, {%8,%9}, {%0,%1,%2,%3};" \
        : "+f"((c)[0]), "+f"((c)[1]), "+f"((c)[2]), "+f"((c)[3]) \
        : "r"((a)[0]), "r"((a)[1]), "r"((a)[2]), "r"((a)[3]), "r"(b0), "r"(b1))

#define LDMATX4(r, ad) \
    asm volatile("ldmatrix.sync.aligned.m8n8.x4.shared.b16 {%0,%1,%2,%3}, [%4];" \
        : "=r"((r)[0]), "=r"((r)[1]), "=r"((r)[2]), "=r"((r)[3]) : "r"(ad))

// ---- double-float exact-ish dot (ranking only) ----
__device__ __forceinline__ void two_sum(float a, float b, float& s, float& e) {
    s = a + b;
    float bv = s - a;
    e = (a - (s - bv)) + (b - bv);
}
__device__ __forceinline__ double df_dot_warp(const float* __restrict__ x,
                                              const float* __restrict__ w,
                                              int lane) {
    float hi = 0.f, lo = 0.f;
    for (int k = lane; k < DM; k += 32) {
        float xv = x[k], wv = w[k];
        float p  = xv * wv;
        float pe = fmaf(xv, wv, -p);
        float s, e;
        two_sum(hi, p, s, e);
        lo += e + pe;
        hi = s;
    }
#pragma unroll
    for (int off = 16; off; off >>= 1) {
        float h2 = __shfl_down_sync(0xFFFFFFFFu, hi, off);
        float l2 = __shfl_down_sync(0xFFFFFFFFu, lo, off);
        float s, e;
        two_sum(hi, h2, s, e);
        lo = lo + l2 + e;
        hi = s;
    }
    return (double)hi + (double)lo;     // lane 0
}
// ---- plain fp32 dot (value recompute) ----
__device__ __forceinline__ float fp32_dot_warp(const float* __restrict__ x,
                                               const float* __restrict__ w,
                                               int lane) {
    float acc = 0.f;
    for (int k = lane; k < DM; k += 32) acc = fmaf(x[k], w[k], acc);
#pragma unroll
    for (int off = 16; off; off >>= 1)
        acc += __shfl_down_sync(0xFFFFFFFFu, acc, off);
    return acc;                          // lane 0
}

// ============================================================
// Prepass 1: x -> bf16
// ============================================================
__global__ __launch_bounds__(256) void split_x_kernel(const float* __restrict__ x)
{
    long i = (long)blockIdx.x * 256 + threadIdx.x;
    float4 v = ((const float4*)x)[i];
    __nv_bfloat16 h[4];
    h[0] = __float2bfloat16(v.x); h[1] = __float2bfloat16(v.y);
    h[2] = __float2bfloat16(v.z); h[3] = __float2bfloat16(v.w);
    ((uint2*)g_Abf)[i] = *(uint2*)h;
}

// ============================================================
// Prepass 2: transpose W_enc [DM,DH] -> [DH,DM] fp32 + bf16
// ============================================================
__global__ __launch_bounds__(256) void split_w_kernel(const float* __restrict__ W)
{
    __shared__ float s[32][33];
    const int n0 = blockIdx.x * 32, k0 = blockIdx.y * 32;
    const int tx = threadIdx.x, ty = threadIdx.y;
#pragma unroll
    for (int i = 0; i < 4; i++)
        s[ty + 8 * i][tx] = W[(long)(k0 + ty + 8 * i) * DH + n0 + tx];
    __syncthreads();
#pragma unroll
    for (int i = 0; i < 4; i++) {
        const int n = n0 + ty + 8 * i, k = k0 + tx;
        const float f = s[tx][ty + 8 * i];
        g_WT [(long)n * DM + k] = f;
        g_Bbf[(long)n * DM + k] = __float2bfloat16(f);
    }
}

// ============================================================
// Encode GEMM: bf16 HMMA — epilogue now writes quantized 16-bit z.
// ============================================================
#define BM 128
#define BN 256
#define BKG 64
#define ASTG 16384
#define STAGE 49152
#define NSTG 3
#define SMEM_DYN (NSTG * STAGE)

__device__ __forceinline__ unsigned short q16z(float z) {
    z = fmaxf(z, 0.f);
    return (unsigned short)(__float_as_uint(z) >> 16);
}

__global__ __launch_bounds__(256, 1) void encode_mma_kernel(const float* __restrict__ bias)
{
    extern __shared__ __align__(1024) char smem[];
    const uint32_t smb = smem_u32(smem);
    const int tid = threadIdx.x, lane = tid & 31, wid = tid >> 5;
    const int wm = wid >> 2, wn = wid & 3;
    const int m0 = blockIdx.y * BM, n0 = blockIdx.x * BN;

    int arow[4], bro[8];
    uint32_t asw[4], bsw[8];
    long asrc[4], bsrc[8];
#pragma unroll
    for (int i = 0; i < 4; i++) {
        int c = tid + 256 * i;
        arow[i] = c >> 3;
        int ch = c & 7;
        asw[i] = SWZ128((uint32_t)(arow[i] * 128 + ch * 16));
        asrc[i] = (long)(m0 + arow[i]) * DM + ch * 8;
    }
#pragma unroll
    for (int i = 0; i < 8; i++) {
        int c = tid + 256 * i;
        bro[i] = c >> 3;
        int ch = c & 7;
        bsw[i] = SWZ128((uint32_t)(bro[i] * 128 + ch * 16));
        bsrc[i] = (long)(n0 + bro[i]) * DM + ch * 8;
    }

    const int rowA = wm * 64 + (lane & 7) + ((lane >> 3) & 1) * 8;
    const int kbA  = ((lane >> 4) & 1) * 16;
    const int rowB = wn * 64 + (lane & 7) + ((lane >> 4) & 1) * 8;
    const int kbB  = ((lane >> 3) & 1) * 16;

    float acc[4][8][4];
#pragma unroll
    for (int m = 0; m < 4; m++)
#pragma unroll
        for (int n = 0; n < 8; n++)
#pragma unroll
            for (int r = 0; r < 4; r++) acc[m][n][r] = 0.f;

    auto issue = [&](int k0, int s) {
        const uint32_t As = smb + s * STAGE;
        const uint32_t Bs = As + ASTG;
#pragma unroll
        for (int i = 0; i < 4; i++)
            CPASYNC16(As + asw[i], (const char*)(g_Abf + asrc[i] + k0));
#pragma unroll
        for (int i = 0; i < 8; i++)
            CPASYNC16(Bs + bsw[i], (const char*)(g_Bbf + bsrc[i] + k0));
    };

    auto compute = [&](int s) {
        const uint32_t As = smb + s * STAGE;
        const uint32_t Bs = As + ASTG;
#pragma unroll
        for (int ks = 0; ks < 4; ks++) {
            uint32_t a[4][4], bq[4][4];
#pragma unroll
            for (int mt = 0; mt < 4; mt++) {
                uint32_t off = (uint32_t)((rowA + mt * 16) * 128 + ks * 32 + kbA);
                LDMATX4(a[mt], As + SWZ128(off));
            }
#pragma unroll
            for (int j = 0; j < 4; j++) {
                uint32_t off = (uint32_t)((rowB + j * 16) * 128 + ks * 32 + kbB);
                LDMATX4(bq[j], Bs + SWZ128(off));
            }
#pragma unroll
            for (int mt = 0; mt < 4; mt++)
#pragma unroll
                for (int j = 0; j < 4; j++) {
                    MMA16816(acc[mt][2 * j],     a[mt], bq[j][0], bq[j][1]);
                    MMA16816(acc[mt][2 * j + 1], a[mt], bq[j][2], bq[j][3]);
                }
        }
    };

    issue(0, 0);   CP_COMMIT();
    issue(64, 1);  CP_COMMIT();

    const int NIT = DM / BKG;
    for (int i = 0; i < NIT; i++) {
        if (i < NIT - 2) asm volatile("cp.async.wait_group 1;" ::: "memory");
        else             asm volatile("cp.async.wait_group 0;" ::: "memory");
        __syncthreads();
        compute(i % NSTG);
        if (i + 2 < NIT) {
            issue((i + 2) * BKG, (i + 2) % NSTG);
            CP_COMMIT();
        }
    }

    // ---- epilogue: bias + ReLU -> quantized 16-bit store ----
    const int r0  = m0 + wm * 64 + (lane >> 2);
    const int c0  = n0 + wn * 64 + (lane & 3) * 2;
#pragma unroll
    for (int nt = 0; nt < 8; nt++) {
        const int col = c0 + nt * 8;
        const float2 bv = *(const float2*)&bias[col];
#pragma unroll
        for (int mt = 0; mt < 4; mt++) {
            const int r = r0 + mt * 16;
            ushort2 o0, o1;
            o0.x = q16z(acc[mt][nt][0] + bv.x);
            o0.y = q16z(acc[mt][nt][1] + bv.y);
            o1.x = q16z(acc[mt][nt][2] + bv.x);
            o1.y = q16z(acc[mt][nt][3] + bv.y);
            *(ushort2*)&g_zq[(long)r * DH + col]       = o0;
            *(ushort2*)&g_zq[(long)(r + 8) * DH + col] = o1;
        }
    }
}

// ============================================================
// Fused TopK + decode. Quantized staging (32 KB), moment seed,
// bitonic rank-64, df window refinement, fp32 value recompute,
// then in-kernel decode from smem selection.
// ============================================================
__global__ __launch_bounds__(256) void topk_decode_kernel(
    const float* __restrict__ X,
    const float* __restrict__ benc,
    const float* __restrict__ Wd,
    const float* __restrict__ bd,
    float* __restrict__ Y)
{
    extern __shared__ unsigned smq[];   // 32 KB: DH 16-bit values, 2 per uint
    __shared__ float  s_x[DM];          // 4 KB x row
    __shared__ unsigned s_key[512];
    __shared__ int    s_cidx[CMAX];
    __shared__ double s_cval[CMAX];
    __shared__ int    s_selidx[KSEL];
    __shared__ float  s_selval[KSEL];
    __shared__ float  s_p1[8], s_p2[8];
    __shared__ int    s_red, s_na, s_nc, s_cnt;
    __shared__ float  s_t;

    const int row = blockIdx.x;
    const int tid = threadIdx.x;
    const int wid = tid >> 5, lane = tid & 31;
    const float* xr = X + (long)row * DM;

    for (int k = tid; k < DM; k += 256) s_x[k] = xr[k];

    // ---- stage quantized row (uint4 copy) + moments ----
    {
        const uint4* zq4 = (const uint4*)(g_zq + (long)row * DH);
        uint4* s4 = (uint4*)smq;
        float sum = 0.f, ss = 0.f;
#pragma unroll 2
        for (int i = tid; i < DH / 8; i += 256) {
            uint4 u = zq4[i];
            s4[i] = u;
            const unsigned ws[4] = {u.x, u.y, u.z, u.w};
#pragma unroll
            for (int j = 0; j < 4; j++) {
                float a = __uint_as_float(ws[j] << 16);
                float b = __uint_as_float(ws[j] & 0xFFFF0000u);
                sum += a + b;
                ss  += a * a + b * b;
            }
        }
#pragma unroll
        for (int o = 16; o; o >>= 1) {
            sum += __shfl_xor_sync(0xFFFFFFFFu, sum, o);
            ss  += __shfl_xor_sync(0xFFFFFFFFu, ss,  o);
        }
        if (lane == 0) { s_p1[wid] = sum; s_p2[wid] = ss; }
        __syncthreads();
        if (tid == 0) {
            float S = 0.f, S2 = 0.f;
#pragma unroll
            for (int w = 0; w < 8; w++) { S += s_p1[w]; S2 += s_p2[w]; }
            const float mu = S / DH;
            const float var = fmaxf(S2 / DH - mu * mu, 0.f);
            s_t = mu + 3.0f * sqrtf(var);
        }
        __syncthreads();
    }

    // count(v >= q16) over packed smem
    auto count_ge = [&](unsigned q16) -> int {
        if (tid == 0) s_red = 0;
        __syncthreads();
        int cc = 0;
#pragma unroll 8
        for (int i = 0; i < DH / 512; i++) {
            const unsigned u = smq[i * 256 + tid];
            cc += ((u & 0xFFFFu) >= q16) ? 1 : 0;
            cc += ((u >> 16)     >= q16) ? 1 : 0;
        }
#pragma unroll
        for (int o = 16; o; o >>= 1) cc += __shfl_xor_sync(0xFFFFFFFFu, cc, o);
        if (lane == 0) atomicAdd(&s_red, cc);
        __syncthreads();
        const int c = s_red;
        __syncthreads();
        return c;
    };

    // ---- moment-guided threshold iteration ----
    float t = s_t;
    unsigned tb16 = 0;
    bool ok = false;
    for (int it = 0; it < 24; ++it) {
        if (!(t > 4.f * RWIN)) break;
        const unsigned q16 = __float_as_uint(t) >> 16;
        const int c = count_ge(q16);
        if (c >= KSEL && c <= CBAND) { tb16 = q16; ok = true; break; }
        t = (c < KSEL) ? t * 0.85f : t * 1.12f;
    }

    bool fast = false;

    if (ok) {
        // ---- compact candidate values (order-free) ----
        if (tid == 0) s_nc = 0;
        __syncthreads();
        for (int i = 0; i < DH / 512; i++) {
            const unsigned u = smq[i * 256 + tid];
            const unsigned v0 = u & 0xFFFFu, v1 = u >> 16;
            if (v0 >= tb16) { int p = atomicAdd(&s_nc, 1); s_key[p] = v0; }
            if (v1 >= tb16) { int p = atomicAdd(&s_nc, 1); s_key[p] = v1; }
        }
        __syncthreads();
        const int cc0 = s_nc;
        for (int p = tid; p < 512; p += 256)
            if (p >= cc0) s_key[p] = 0u;
        __syncthreads();

        // ---- bitonic sort 512 values, descending ----
        for (int k = 2; k <= 512; k <<= 1) {
            for (int j = k >> 1; j; j >>= 1) {
#pragma unroll
                for (int rr = 0; rr < 2; rr++) {
                    const int i2 = tid + 256 * rr;
                    const int p = i2 ^ j;
                    if (p > i2) {
                        unsigned a = s_key[i2], b = s_key[p];
                        const bool up = ((i2 & k) == 0);
                        if (up ? (a < b) : (a > b)) { s_key[i2] = b; s_key[p] = a; }
                    }
                }
                __syncthreads();
            }
        }

        const unsigned h64 = s_key[63];
        const float tf_lo = __uint_as_float(h64 << 16);
        const float qw = __uint_as_float((h64 + 1) << 16) - tf_lo;

        if (tf_lo > 2.0f * RWIN) {
            const unsigned hib16 = __float_as_uint(tf_lo + qw + RWIN) >> 16;
            const unsigned lob16 = __float_as_uint(tf_lo - RWIN) >> 16;
            if (tid == 0) { s_na = 0; s_nc = 0; }
            __syncthreads();
            for (int i = 0; i < DH / 512; i++) {
                const unsigned u = smq[i * 256 + tid];
                const int gi0 = (i * 256 + tid) * 2;
#pragma unroll
                for (int h = 0; h < 2; h++) {
                    const unsigned v = h ? (u >> 16) : (u & 0xFFFFu);
                    const int gi = gi0 + h;
                    if (v > hib16) {
                        int p = atomicAdd(&s_na, 1);
                        s_selidx[p] = gi;
                    } else if (v >= lob16) {
                        int p = atomicAdd(&s_nc, 1);
                        if (p < CMAX) s_cidx[p] = gi;
                    }
                }
            }
            __syncthreads();
            const int cA = s_na, cC = s_nc;
            if (cC <= CMAX) {
                // df-exact values for candidates (warp per candidate)
                for (int c2 = wid; c2 < cC; c2 += 8) {
                    const int fi = s_cidx[c2];
                    double d = df_dot_warp(s_x, g_WT + (long)fi * DM, lane);
                    if (lane == 0) {
                        d += (double)benc[fi];
                        s_cval[c2] = d > 0.0 ? d : 0.0;
                    }
                }
                __syncthreads();
                // exact ranking (value desc, index asc); keep top need
                const int need = KSEL - cA;
                for (int c2 = tid; c2 < cC; c2 += 256) {
                    const double v = s_cval[c2];
                    const int fi = s_cidx[c2];
                    int rank = 0;
                    for (int c3 = 0; c3 < cC; c3++) {
                        const double u = s_cval[c3];
                        if (u > v || (u == v && s_cidx[c3] < fi)) rank++;
                    }
                    if (rank < need) s_selidx[cA + rank] = fi;
                }
                __syncthreads();
                // fp32 recompute of ALL selected values
                for (int j = wid; j < KSEL; j += 8) {
                    const int fi = s_selidx[j];
                    float d = fp32_dot_warp(s_x, g_WT + (long)fi * DM, lane);
                    if (lane == 0) {
                        d += benc[fi];
                        s_selval[j] = fmaxf(d, 0.f);
                    }
                }
                if (tid == 0) s_cnt = KSEL;
                fast = true;
            }
            __syncthreads();
        }
    }

    if (!fast) {
        // ---- fallback on quantized data (degenerate rows; cold) ----
        // q = quantized rank-64 threshold via 16-step binary search
        unsigned qlo = 1u, qhi = 0x7F80u;
        if (count_ge(1u) < KSEL) {
            // fewer than KSEL positives: take them all (zeros contribute 0)
            if (tid == 0) s_na = 0;
            __syncthreads();
            for (int i = 0; i < DH / 512; i++) {
                const unsigned u = smq[i * 256 + tid];
                const int gi0 = (i * 256 + tid) * 2;
#pragma unroll
                for (int h = 0; h < 2; h++) {
                    const unsigned v = h ? (u >> 16) : (u & 0xFFFFu);
                    if (v >= 1u) {
                        int p = atomicAdd(&s_na, 1);
                        s_selidx[p] = gi0 + h;
                    }
                }
            }
            __syncthreads();
            if (tid == 0) s_cnt = s_na;
        } else {
            while (qlo < qhi) {
                unsigned mid = qlo + ((qhi - qlo + 1) >> 1);
                if (count_ge(mid) >= KSEL) qlo = mid; else qhi = mid - 1;
            }
            const unsigned q = qlo;
            // strict-greater set (< KSEL), then ties fill to KSEL
            if (tid == 0) s_na = 0;
            __syncthreads();
            for (int i = 0; i < DH / 512; i++) {
                const unsigned u = smq[i * 256 + tid];
                const int gi0 = (i * 256 + tid) * 2;
#pragma unroll
                for (int h = 0; h < 2; h++) {
                    const unsigned v = h ? (u >> 16) : (u & 0xFFFFu);
                    if (v > q) {
                        int p = atomicAdd(&s_na, 1);
                        s_selidx[p] = gi0 + h;
                    }
                }
            }
            __syncthreads();
            for (int i = 0; i < DH / 512; i++) {
                const unsigned u = smq[i * 256 + tid];
                const int gi0 = (i * 256 + tid) * 2;
#pragma unroll
                for (int h = 0; h < 2; h++) {
                    const unsigned v = h ? (u >> 16) : (u & 0xFFFFu);
                    if (v == q) {
                        int p = atomicAdd(&s_na, 1);
                        if (p < KSEL) s_selidx[p] = gi0 + h;
                    }
                }
            }
            __syncthreads();
            if (tid == 0) s_cnt = KSEL;
        }
        __syncthreads();
        // fp32 recompute of selected values
        const int scnt = s_cnt;
        for (int j = wid; j < scnt; j += 8) {
            const int fi = s_selidx[j];
            float d = fp32_dot_warp(s_x, g_WT + (long)fi * DM, lane);
            if (lane == 0) {
                d += benc[fi];
                s_selval[j] = fmaxf(d, 0.f);
            }
        }
    }

    // ---- fused decode: y = b_dec + sum val_j * W_dec[idx_j,:] ----
    __syncthreads();
    const int cnt = s_cnt;
    float4 acc = ((const float4*)bd)[tid];
#pragma unroll 4
    for (int j = 0; j < cnt; j++) {
        const float v = s_selval[j];
        const float4 wv = ((const float4*)(Wd + (long)s_selidx[j] * DM))[tid];
        acc.x = fmaf(v, wv.x, acc.x);
        acc.y = fmaf(v, wv.y, acc.y);
        acc.z = fmaf(v, wv.z, acc.z);
        acc.w = fmaf(v, wv.w, acc.w);
    }
    ((float4*)Y)[(long)row * (DM / 4) + tid] = acc;
}

// ============================================================
extern "C" void kernel_launch(void* const* d_in, const int* in_sizes, int n_in,
                              void* d_out, int out_size)
{
    const float* x     = (const float*)d_in[0];
    const float* W_enc = (const float*)d_in[1];
    const float* b_enc = (const float*)d_in[2];
    const float* W_dec = (const float*)d_in[3];
    const float* b_dec = (const float*)d_in[4];
    float* y = (float*)d_out;

    split_x_kernel<<<(TOK * DM) / (256 * 4), 256>>>(x);
    split_w_kernel<<<dim3(DH / 32, DM / 32), dim3(32, 8)>>>(W_enc);

    cudaFuncSetAttribute(encode_mma_kernel,
                         cudaFuncAttributeMaxDynamicSharedMemorySize, SMEM_DYN);
    dim3 ge(DH / BN, TOK / BM);   // (64, 32)
    encode_mma_kernel<<<ge, 256, SMEM_DYN>>>(b_enc);

    cudaFuncSetAttribute(topk_decode_kernel,
                         cudaFuncAttributeMaxDynamicSharedMemorySize, DH * 2);
    topk_decode_kernel<<<TOK, 256, DH * 2>>>(x, b_enc, W_dec, b_dec, y);
}

// round 14
// speedup vs baseline: 2.3964x; 1.0376x over previous
#include <cuda_runtime.h>
#include <cuda_bf16.h>
#include <cuda_fp16.h>
#include <cstdint>

#define TOK   4096
#define DH    16384
#define DM    1024
#define KSEL  64
#define CMAX  192
#define CBAND 448
#define RWIN  1.5e-2f

// ---- scratch (device globals; no runtime allocation) ----
__device__ __align__(16) unsigned short g_zq[(long)TOK * DH];  // 128 MB quantized z
__device__ __align__(16) __nv_bfloat16 g_Abf[(long)TOK * DM];
__device__ __align__(16) __nv_bfloat16 g_Bbf[(long)DH * DM];   // W_enc^T bf16 (GEMM)
__device__ __align__(16) __half        g_Whi[(long)DH * DM];   // W_enc^T fp16 hi
__device__ __align__(16) __half        g_Wlo[(long)DH * DM];   // W_enc^T fp16 lo (x1024)
__device__ __align__(16) __half        g_Wd16[(long)DH * DM];  // W_dec fp16

// ============================================================
// helpers
// ============================================================
__device__ __forceinline__ uint32_t smem_u32(const void* p) {
    uint32_t a;
    asm("{ .reg .u64 t; cvta.to.shared.u64 t, %1; cvt.u32.u64 %0, t; }"
        : "=r"(a) : "l"(p));
    return a;
}
#define SWZ128(o) ((o) ^ (((o) >> 3) & 0x70))

#define CPASYNC16(dst, src) \
    asm volatile("cp.async.cg.shared.global [%0], [%1], 16;" \
                 :: "r"(dst), "l"(src) : "memory")
#define CP_COMMIT() asm volatile("cp.async.commit_group;" ::: "memory")

#define MMA16816(c, a, b0, b1) \
    asm volatile("mma.sync.aligned.m16n8k16.row.col.f32.bf16.bf16.f32 " \
        "{%0,%1,%2,%3}, {%4,%5,%6,%7}, {%8,%9}, {%0,%1,%2,%3};" \
        : "+f"((c)[0]), "+f"((c)[1]), "+f"((c)[2]), "+f"((c)[3]) \
        : "r"((a)[0]), "r"((a)[1]), "r"((a)[2]), "r"((a)[3]), "r"(b0), "r"(b1))

#define LDMATX4(r, ad) \
    asm volatile("ldmatrix.sync.aligned.m8n8.x4.shared.b16 {%0,%1,%2,%3}, [%4];" \
        : "=r"((r)[0]), "=r"((r)[1]), "=r"((r)[2]), "=r"((r)[3]) : "r"(ad))

__device__ __forceinline__ void two_sum(float a, float b, float& s, float& e) {
    s = a + b;
    float bv = s - a;
    e = (a - (s - bv)) + (b - bv);
}

// ---- near-exact ranking dot: TwoProd on fp16-hi + scaled fp16-lo ----
__device__ __forceinline__ double dfh_dot_warp(const float* __restrict__ x,
                                               const __half* __restrict__ whi,
                                               const __half* __restrict__ wlo,
                                               int lane) {
    float shi = 0.f, slo = 0.f, lacc = 0.f;
#pragma unroll
    for (int i = 0; i < 16; i++) {
        const int k = 2 * (lane + 32 * i);
        const float2 hf = __half22float2(*(const __half2*)&whi[k]);
        const float2 lf = __half22float2(*(const __half2*)&wlo[k]);
        const float x0 = x[k], x1 = x[k + 1];
        float p, pe, s, e;
        p = x0 * hf.x; pe = fmaf(x0, hf.x, -p);
        two_sum(shi, p, s, e); slo += e + pe; shi = s;
        p = x1 * hf.y; pe = fmaf(x1, hf.y, -p);
        two_sum(shi, p, s, e); slo += e + pe; shi = s;
        lacc = fmaf(x0, lf.x, lacc);
        lacc = fmaf(x1, lf.y, lacc);
    }
#pragma unroll
    for (int off = 16; off; off >>= 1) {
        float h2 = __shfl_down_sync(0xFFFFFFFFu, shi, off);
        float l2 = __shfl_down_sync(0xFFFFFFFFu, slo, off);
        float a2 = __shfl_down_sync(0xFFFFFFFFu, lacc, off);
        float s, e;
        two_sum(shi, h2, s, e);
        slo = slo + l2 + e;
        shi = s;
        lacc += a2;
    }
    return (double)shi + (double)slo + (double)lacc * 0.0009765625;   // lane 0
}

// ---- fp32 dot over fp16-hi weights (value recompute) ----
__device__ __forceinline__ float dot16_warp(const float* __restrict__ x,
                                            const __half* __restrict__ w,
                                            int lane) {
    float acc = 0.f;
#pragma unroll
    for (int i = 0; i < 16; i++) {
        const int k = 2 * (lane + 32 * i);
        const float2 f = __half22float2(*(const __half2*)&w[k]);
        acc = fmaf(x[k],     f.x, acc);
        acc = fmaf(x[k + 1], f.y, acc);
    }
#pragma unroll
    for (int off = 16; off; off >>= 1)
        acc += __shfl_down_sync(0xFFFFFFFFu, acc, off);
    return acc;                          // lane 0
}

// ============================================================
// Prepass 1: x -> bf16
// ============================================================
__global__ __launch_bounds__(256) void split_x_kernel(const float* __restrict__ x)
{
    long i = (long)blockIdx.x * 256 + threadIdx.x;
    float4 v = ((const float4*)x)[i];
    __nv_bfloat16 h[4];
    h[0] = __float2bfloat16(v.x); h[1] = __float2bfloat16(v.y);
    h[2] = __float2bfloat16(v.z); h[3] = __float2bfloat16(v.w);
    ((uint2*)g_Abf)[i] = *(uint2*)h;
}

// ============================================================
// Prepass 2: transpose W_enc [DM,DH] -> [DH,DM] bf16 + fp16 hi/lo
// ============================================================
__global__ __launch_bounds__(256) void split_w_kernel(const float* __restrict__ W)
{
    __shared__ float s[32][33];
    const int n0 = blockIdx.x * 32, k0 = blockIdx.y * 32;
    const int tx = threadIdx.x, ty = threadIdx.y;
#pragma unroll
    for (int i = 0; i < 4; i++)
        s[ty + 8 * i][tx] = W[(long)(k0 + ty + 8 * i) * DH + n0 + tx];
    __syncthreads();
#pragma unroll
    for (int i = 0; i < 4; i++) {
        const int n = n0 + ty + 8 * i, k = k0 + tx;
        const float f = s[tx][ty + 8 * i];
        const __half h = __float2half(f);
        const float l32 = (f - __half2float(h)) * 1024.f;
        g_Whi[(long)n * DM + k] = h;
        g_Wlo[(long)n * DM + k] = __float2half(l32);
        g_Bbf[(long)n * DM + k] = __float2bfloat16(f);
    }
}

// ============================================================
// Prepass 3: W_dec fp32 -> fp16 (same layout)
// ============================================================
__global__ __launch_bounds__(256) void split_wd_kernel(const float* __restrict__ Wd)
{
    long i = (long)blockIdx.x * 256 + threadIdx.x;   // float4 index
    float4 v = ((const float4*)Wd)[i];
    __half h[4];
    h[0] = __float2half(v.x); h[1] = __float2half(v.y);
    h[2] = __float2half(v.z); h[3] = __float2half(v.w);
    ((uint2*)g_Wd16)[i] = *(uint2*)h;
}

// ============================================================
// Encode GEMM: bf16 HMMA, quantized 16-bit z epilogue (R13).
// ============================================================
#define BM 128
#define BN 256
#define BKG 64
#define ASTG 16384
#define STAGE 49152
#define NSTG 3
#define SMEM_DYN (NSTG * STAGE)

__device__ __forceinline__ unsigned short q16z(float z) {
    z = fmaxf(z, 0.f);
    return (unsigned short)(__float_as_uint(z) >> 16);
}

__global__ __launch_bounds__(256, 1) void encode_mma_kernel(const float* __restrict__ bias)
{
    extern __shared__ __align__(1024) char smem[];
    const uint32_t smb = smem_u32(smem);
    const int tid = threadIdx.x, lane = tid & 31, wid = tid >> 5;
    const int wm = wid >> 2, wn = wid & 3;
    const int m0 = blockIdx.y * BM, n0 = blockIdx.x * BN;

    int arow[4], bro[8];
    uint32_t asw[4], bsw[8];
    long asrc[4], bsrc[8];
#pragma unroll
    for (int i = 0; i < 4; i++) {
        int c = tid + 256 * i;
        arow[i] = c >> 3;
        int ch = c & 7;
        asw[i] = SWZ128((uint32_t)(arow[i] * 128 + ch * 16));
        asrc[i] = (long)(m0 + arow[i]) * DM + ch * 8;
    }
#pragma unroll
    for (int i = 0; i < 8; i++) {
        int c = tid + 256 * i;
        bro[i] = c >> 3;
        int ch = c & 7;
        bsw[i] = SWZ128((uint32_t)(bro[i] * 128 + ch * 16));
        bsrc[i] = (long)(n0 + bro[i]) * DM + ch * 8;
    }

    const int rowA = wm * 64 + (lane & 7) + ((lane >> 3) & 1) * 8;
    const int kbA  = ((lane >> 4) & 1) * 16;
    const int rowB = wn * 64 + (lane & 7) + ((lane >> 4) & 1) * 8;
    const int kbB  = ((lane >> 3) & 1) * 16;

    float acc[4][8][4];
#pragma unroll
    for (int m = 0; m < 4; m++)
#pragma unroll
        for (int n = 0; n < 8; n++)
#pragma unroll
            for (int r = 0; r < 4; r++) acc[m][n][r] = 0.f;

    auto issue = [&](int k0, int s) {
        const uint32_t As = smb + s * STAGE;
        const uint32_t Bs = As + ASTG;
#pragma unroll
        for (int i = 0; i < 4; i++)
            CPASYNC16(As + asw[i], (const char*)(g_Abf + asrc[i] + k0));
#pragma unroll
        for (int i = 0; i < 8; i++)
            CPASYNC16(Bs + bsw[i], (const char*)(g_Bbf + bsrc[i] + k0));
    };

    auto compute = [&](int s) {
        const uint32_t As = smb + s * STAGE;
        const uint32_t Bs = As + ASTG;
#pragma unroll
        for (int ks = 0; ks < 4; ks++) {
            uint32_t a[4][4], bq[4][4];
#pragma unroll
            for (int mt = 0; mt < 4; mt++) {
                uint32_t off = (uint32_t)((rowA + mt * 16) * 128 + ks * 32 + kbA);
                LDMATX4(a[mt], As + SWZ128(off));
            }
#pragma unroll
            for (int j = 0; j < 4; j++) {
                uint32_t off = (uint32_t)((rowB + j * 16) * 128 + ks * 32 + kbB);
                LDMATX4(bq[j], Bs + SWZ128(off));
            }
#pragma unroll
            for (int mt = 0; mt < 4; mt++)
#pragma unroll
                for (int j = 0; j < 4; j++) {
                    MMA16816(acc[mt][2 * j],     a[mt], bq[j][0], bq[j][1]);
                    MMA16816(acc[mt][2 * j + 1], a[mt], bq[j][2], bq[j][3]);
                }
        }
    };

    issue(0, 0);   CP_COMMIT();
    issue(64, 1);  CP_COMMIT();

    const int NIT = DM / BKG;
    for (int i = 0; i < NIT; i++) {
        if (i < NIT - 2) asm volatile("cp.async.wait_group 1;" ::: "memory");
        else             asm volatile("cp.async.wait_group 0;" ::: "memory");
        __syncthreads();
        compute(i % NSTG);
        if (i + 2 < NIT) {
            issue((i + 2) * BKG, (i + 2) % NSTG);
            CP_COMMIT();
        }
    }

    const int r0  = m0 + wm * 64 + (lane >> 2);
    const int c0  = n0 + wn * 64 + (lane & 3) * 2;
#pragma unroll
    for (int nt = 0; nt < 8; nt++) {
        const int col = c0 + nt * 8;
        const float2 bv = *(const float2*)&bias[col];
#pragma unroll
        for (int mt = 0; mt < 4; mt++) {
            const int r = r0 + mt * 16;
            ushort2 o0, o1;
            o0.x = q16z(acc[mt][nt][0] + bv.x);
            o0.y = q16z(acc[mt][nt][1] + bv.y);
            o1.x = q16z(acc[mt][nt][2] + bv.x);
            o1.y = q16z(acc[mt][nt][3] + bv.y);
            *(ushort2*)&g_zq[(long)r * DH + col]       = o0;
            *(ushort2*)&g_zq[(long)(r + 8) * DH + col] = o1;
        }
    }
}

// ============================================================
// Fused TopK + decode (R13 structure, fp16 weight paths).
// ============================================================
__global__ __launch_bounds__(256) void topk_decode_kernel(
    const float* __restrict__ X,
    const float* __restrict__ benc,
    const float* __restrict__ bd,
    float* __restrict__ Y)
{
    extern __shared__ unsigned smq[];   // 32 KB: DH 16-bit values
    __shared__ float  s_x[DM];
    __shared__ unsigned s_key[512];
    __shared__ int    s_cidx[CMAX];
    __shared__ double s_cval[CMAX];
    __shared__ int    s_selidx[KSEL];
    __shared__ float  s_selval[KSEL];
    __shared__ float  s_p1[8], s_p2[8];
    __shared__ int    s_red, s_na, s_nc, s_cnt;
    __shared__ float  s_t;

    const int row = blockIdx.x;
    const int tid = threadIdx.x;
    const int wid = tid >> 5, lane = tid & 31;
    const float* xr = X + (long)row * DM;

    for (int k = tid; k < DM; k += 256) s_x[k] = xr[k];

    // ---- stage quantized row + moments ----
    {
        const uint4* zq4 = (const uint4*)(g_zq + (long)row * DH);
        uint4* s4 = (uint4*)smq;
        float sum = 0.f, ss = 0.f;
#pragma unroll 2
        for (int i = tid; i < DH / 8; i += 256) {
            uint4 u = zq4[i];
            s4[i] = u;
            const unsigned ws[4] = {u.x, u.y, u.z, u.w};
#pragma unroll
            for (int j = 0; j < 4; j++) {
                float a = __uint_as_float(ws[j] << 16);
                float b = __uint_as_float(ws[j] & 0xFFFF0000u);
                sum += a + b;
                ss  += a * a + b * b;
            }
        }
#pragma unroll
        for (int o = 16; o; o >>= 1) {
            sum += __shfl_xor_sync(0xFFFFFFFFu, sum, o);
            ss  += __shfl_xor_sync(0xFFFFFFFFu, ss,  o);
        }
        if (lane == 0) { s_p1[wid] = sum; s_p2[wid] = ss; }
        __syncthreads();
        if (tid == 0) {
            float S = 0.f, S2 = 0.f;
#pragma unroll
            for (int w = 0; w < 8; w++) { S += s_p1[w]; S2 += s_p2[w]; }
            const float mu = S / DH;
            const float var = fmaxf(S2 / DH - mu * mu, 0.f);
            s_t = mu + 3.0f * sqrtf(var);
        }
        __syncthreads();
    }

    auto count_ge = [&](unsigned q16) -> int {
        if (tid == 0) s_red = 0;
        __syncthreads();
        int cc = 0;
#pragma unroll 8
        for (int i = 0; i < DH / 512; i++) {
            const unsigned u = smq[i * 256 + tid];
            cc += ((u & 0xFFFFu) >= q16) ? 1 : 0;
            cc += ((u >> 16)     >= q16) ? 1 : 0;
        }
#pragma unroll
        for (int o = 16; o; o >>= 1) cc += __shfl_xor_sync(0xFFFFFFFFu, cc, o);
        if (lane == 0) atomicAdd(&s_red, cc);
        __syncthreads();
        const int c = s_red;
        __syncthreads();
        return c;
    };

    // ---- moment-guided threshold iteration ----
    float t = s_t;
    unsigned tb16 = 0;
    bool ok = false;
    for (int it = 0; it < 24; ++it) {
        if (!(t > 4.f * RWIN)) break;
        const unsigned q16 = __float_as_uint(t) >> 16;
        const int c = count_ge(q16);
        if (c >= KSEL && c <= CBAND) { tb16 = q16; ok = true; break; }
        t = (c < KSEL) ? t * 0.85f : t * 1.12f;
    }

    bool fast = false;

    if (ok) {
        if (tid == 0) s_nc = 0;
        __syncthreads();
        for (int i = 0; i < DH / 512; i++) {
            const unsigned u = smq[i * 256 + tid];
            const unsigned v0 = u & 0xFFFFu, v1 = u >> 16;
            if (v0 >= tb16) { int p = atomicAdd(&s_nc, 1); s_key[p] = v0; }
            if (v1 >= tb16) { int p = atomicAdd(&s_nc, 1); s_key[p] = v1; }
        }
        __syncthreads();
        const int cc0 = s_nc;
        for (int p = tid; p < 512; p += 256)
            if (p >= cc0) s_key[p] = 0u;
        __syncthreads();

        // bitonic sort 512 values, descending
        for (int k = 2; k <= 512; k <<= 1) {
            for (int j = k >> 1; j; j >>= 1) {
#pragma unroll
                for (int rr = 0; rr < 2; rr++) {
                    const int i2 = tid + 256 * rr;
                    const int p = i2 ^ j;
                    if (p > i2) {
                        unsigned a = s_key[i2], b = s_key[p];
                        const bool up = ((i2 & k) == 0);
                        if (up ? (a < b) : (a > b)) { s_key[i2] = b; s_key[p] = a; }
                    }
                }
                __syncthreads();
            }
        }

        const unsigned h64 = s_key[63];
        const float tf_lo = __uint_as_float(h64 << 16);
        const float qw = __uint_as_float((h64 + 1) << 16) - tf_lo;

        if (tf_lo > 2.0f * RWIN) {
            const unsigned hib16 = __float_as_uint(tf_lo + qw + RWIN) >> 16;
            const unsigned lob16 = __float_as_uint(tf_lo - RWIN) >> 16;
            if (tid == 0) { s_na = 0; s_nc = 0; }
            __syncthreads();
            for (int i = 0; i < DH / 512; i++) {
                const unsigned u = smq[i * 256 + tid];
                const int gi0 = (i * 256 + tid) * 2;
#pragma unroll
                for (int h = 0; h < 2; h++) {
                    const unsigned v = h ? (u >> 16) : (u & 0xFFFFu);
                    const int gi = gi0 + h;
                    if (v > hib16) {
                        int p = atomicAdd(&s_na, 1);
                        s_selidx[p] = gi;
                    } else if (v >= lob16) {
                        int p = atomicAdd(&s_nc, 1);
                        if (p < CMAX) s_cidx[p] = gi;
                    }
                }
            }
            __syncthreads();
            const int cA = s_na, cC = s_nc;
            if (cC <= CMAX) {
                // near-exact hi/lo values for candidates (warp per candidate)
                for (int c2 = wid; c2 < cC; c2 += 8) {
                    const int fi = s_cidx[c2];
                    double d = dfh_dot_warp(s_x, g_Whi + (long)fi * DM,
                                            g_Wlo + (long)fi * DM, lane);
                    if (lane == 0) {
                        d += (double)benc[fi];
                        s_cval[c2] = d > 0.0 ? d : 0.0;
                    }
                }
                __syncthreads();
                // exact ranking (value desc, index asc); keep top need
                const int need = KSEL - cA;
                for (int c2 = tid; c2 < cC; c2 += 256) {
                    const double v = s_cval[c2];
                    const int fi = s_cidx[c2];
                    int rank = 0;
                    for (int c3 = 0; c3 < cC; c3++) {
                        const double u = s_cval[c3];
                        if (u > v || (u == v && s_cidx[c3] < fi)) rank++;
                    }
                    if (rank < need) s_selidx[cA + rank] = fi;
                }
                __syncthreads();
                // fp16-hi recompute of ALL selected values
                for (int j = wid; j < KSEL; j += 8) {
                    const int fi = s_selidx[j];
                    float d = dot16_warp(s_x, g_Whi + (long)fi * DM, lane);
                    if (lane == 0) {
                        d += benc[fi];
                        s_selval[j] = fmaxf(d, 0.f);
                    }
                }
                if (tid == 0) s_cnt = KSEL;
                fast = true;
            }
            __syncthreads();
        }
    }

    if (!fast) {
        // ---- fallback on quantized data (degenerate rows; cold) ----
        unsigned qlo = 1u, qhi = 0x7F80u;
        if (count_ge(1u) < KSEL) {
            if (tid == 0) s_na = 0;
            __syncthreads();
            for (int i = 0; i < DH / 512; i++) {
                const unsigned u = smq[i * 256 + tid];
                const int gi0 = (i * 256 + tid) * 2;
#pragma unroll
                for (int h = 0; h < 2; h++) {
                    const unsigned v = h ? (u >> 16) : (u & 0xFFFFu);
                    if (v >= 1u) {
                        int p = atomicAdd(&s_na, 1);
                        s_selidx[p] = gi0 + h;
                    }
                }
            }
            __syncthreads();
            if (tid == 0) s_cnt = s_na;
        } else {
            while (qlo < qhi) {
                unsigned mid = qlo + ((qhi - qlo + 1) >> 1);
                if (count_ge(mid) >= KSEL) qlo = mid; else qhi = mid - 1;
            }
            const unsigned q = qlo;
            if (tid == 0) s_na = 0;
            __syncthreads();
            for (int i = 0; i < DH / 512; i++) {
                const unsigned u = smq[i * 256 + tid];
                const int gi0 = (i * 256 + tid) * 2;
#pragma unroll
                for (int h = 0; h < 2; h++) {
                    const unsigned v = h ? (u >> 16) : (u & 0xFFFFu);
                    if (v > q) {
                        int p = atomicAdd(&s_na, 1);
                        s_selidx[p] = gi0 + h;
                    }
                }
            }
            __syncthreads();
            for (int i = 0; i < DH / 512; i++) {
                const unsigned u = smq[i * 256 + tid];
                const int gi0 = (i * 256 + tid) * 2;
#pragma unroll
                for (int h = 0; h < 2; h++) {
                    const unsigned v = h ? (u >> 16) : (u & 0xFFFFu);
                    if (v == q) {
                        int p = atomicAdd(&s_na, 1);
                        if (p < KSEL) s_selidx[p] = gi0 + h;
                    }
                }
            }
            __syncthreads();
            if (tid == 0) s_cnt = KSEL;
        }
        __syncthreads();
        const int scnt = s_cnt;
        for (int j = wid; j < scnt; j += 8) {
            const int fi = s_selidx[j];
            float d = dot16_warp(s_x, g_Whi + (long)fi * DM, lane);
            if (lane == 0) {
                d += benc[fi];
                s_selval[j] = fmaxf(d, 0.f);
            }
        }
    }

    // ---- fused decode (fp16 W_dec): y = b_dec + sum v_j * Wd[idx_j,:] ----
    __syncthreads();
    const int cnt = s_cnt;
    float4 acc = ((const float4*)bd)[tid];
#pragma unroll 4
    for (int j = 0; j < cnt; j++) {
        const float v = s_selval[j];
        const __half2* wrow = (const __half2*)(g_Wd16 + (long)s_selidx[j] * DM);
        const float2 f0 = __half22float2(wrow[tid * 2]);
        const float2 f1 = __half22float2(wrow[tid * 2 + 1]);
        acc.x = fmaf(v, f0.x, acc.x);
        acc.y = fmaf(v, f0.y, acc.y);
        acc.z = fmaf(v, f1.x, acc.z);
        acc.w = fmaf(v, f1.y, acc.w);
    }
    ((float4*)Y)[(long)row * (DM / 4) + tid] = acc;
}

// ============================================================
extern "C" void kernel_launch(void* const* d_in, const int* in_sizes, int n_in,
                              void* d_out, int out_size)
{
    const float* x     = (const float*)d_in[0];
    const float* W_enc = (const float*)d_in[1];
    const float* b_enc = (const float*)d_in[2];
    const float* W_dec = (const float*)d_in[3];
    const float* b_dec = (const float*)d_in[4];
    float* y = (float*)d_out;

    split_x_kernel<<<(TOK * DM) / (256 * 4), 256>>>(x);
    split_w_kernel<<<dim3(DH / 32, DM / 32), dim3(32, 8)>>>(W_enc);
    split_wd_kernel<<<((long)DH * DM) / (256 * 4), 256>>>(W_dec);

    cudaFuncSetAttribute(encode_mma_kernel,
                         cudaFuncAttributeMaxDynamicSharedMemorySize, SMEM_DYN);
    dim3 ge(DH / BN, TOK / BM);   // (64, 32)
    encode_mma_kernel<<<ge, 256, SMEM_DYN>>>(b_enc);

    cudaFuncSetAttribute(topk_decode_kernel,
                         cudaFuncAttributeMaxDynamicSharedMemorySize, DH * 2);
    topk_decode_kernel<<<TOK, 256, DH * 2>>>(x, b_enc, b_dec, y);
}